// round 13
// baseline (speedup 1.0000x reference)
#include <cuda_runtime.h>
#include <cuda_bf16.h>
#include <math.h>

// Problem constants
#define Bb   4
#define T    128
#define D    512
#define Hh   4
#define DK   128
#define NL   4
#define DFF  2048
#define NC   5

#define M2   1024            // merged towers: 2*Bb*T rows
#define ND   (M2*D)          // 524288

// ---------------- scratch ----------------------------------------------------
#define OFF_X   0
#define OFF_Q   (1*ND)
#define OFF_K   (2*ND)
#define OFF_V   (3*ND)
#define OFF_T0  (4*ND)
#define OFF_T1  (5*ND)
#define OFF_H   (6*ND)
#define OFF_FFN (7*ND)              // M2*DFF = 4*ND
#define OFF_QK  (11*ND)
#define OFF_P   (OFF_QK + 65536)
#define OFF_EQ  (OFF_P + 65536)
#define OFF_EK  (OFF_EQ + 2560)
#define OFF_G   (OFF_EK + 2560)
#define OFF_W   (OFF_G + 32)
#define OFF_PK  (OFF_W + 2560)      // 4*T*D = 262144
#define OFF_T2  (OFF_PK + 262144)
#define OFF_QK2 (OFF_T2 + ND)
#define OFF_PK2 (OFF_QK2 + 65536)
#define SCRATCH_TOTAL (OFF_PK2 + 262144)

__device__ float g_scratch[SCRATCH_TOTAL];

__device__ __forceinline__ float gelu_f(float x) {
    return 0.5f * x * (1.0f + erff(x * 0.7071067811865475f));
}

// ---------------- tf32 / mma / cp.async helpers ------------------------------
__device__ __forceinline__ unsigned f2tf32(float x) {
    unsigned r;
    asm("cvt.rna.tf32.f32 %0, %1;" : "=r"(r) : "f"(x));
    return r;
}
__device__ __forceinline__ void split2(float x, unsigned& hi, unsigned& lo) {
    hi = f2tf32(x);
    lo = f2tf32(x - __uint_as_float(hi));
}
__device__ __forceinline__ float2 split2f(float x) {
    unsigned h, l;
    split2(x, h, l);
    return make_float2(__uint_as_float(h), __uint_as_float(l));
}
__device__ __forceinline__ void mma_tf32(float* c, const unsigned* a, const unsigned* b) {
    asm volatile(
        "mma.sync.aligned.m16n8k8.row.col.f32.tf32.tf32.f32 "
        "{%0,%1,%2,%3},{%4,%5,%6,%7},{%8,%9},{%0,%1,%2,%3};"
        : "+f"(c[0]), "+f"(c[1]), "+f"(c[2]), "+f"(c[3])
        : "r"(a[0]), "r"(a[1]), "r"(a[2]), "r"(a[3]), "r"(b[0]), "r"(b[1]));
}
__device__ __forceinline__ void cp16(void* s, const void* g) {
    unsigned sa = (unsigned)__cvta_generic_to_shared(s);
    asm volatile("cp.async.cg.shared.global [%0], [%1], 16;\n" :: "r"(sa), "l"(g) : "memory");
}
#define CP_COMMIT() asm volatile("cp.async.commit_group;\n" ::: "memory")
#define CP_WAIT(n)  asm volatile("cp.async.wait_group %0;\n" :: "n"(n) : "memory")

// ---------------- pipelined 3xTF32 GEMM, 64x64 tile, BK=32 -------------------
// 2 raw cp.async stages + cooperative split planes (hi,lo float2).
// Mainloop: pure LDS.64 + MMA. 256 thr = 8 warps, grid 2(m) x 4(n), tile 32x16.
#define PADK 36
#define PADN 72
#define SPA  36     // A / trans-B split plane row stride (float2)
#define SPB  68     // non-trans B split plane row stride (float2)

// floats: Araw 2*64*36=4608, Braw 4608 (both layouts), then split planes
#define RAW_FLOATS 9216
#define ASP_F2 (64 * SPA)     // 2304 float2

template<int TRANSB>
__global__ __launch_bounds__(256, 2)
void gemm_tf32(const float* __restrict__ A0, const float* __restrict__ A1, const float* __restrict__ A2,
               const float* __restrict__ W0, const float* __restrict__ W1, const float* __restrict__ W2,
               const float* __restrict__ bias0, const float* __restrict__ bias1, const float* __restrict__ bias2,
               float* __restrict__ C0, float* __restrict__ C1, float* __restrict__ C2,
               int M, int N, int K, int lda, int ldb, int ldc,
               int act, int nH,
               long long sA, long long hA, long long sB, long long hB,
               long long sC, long long hC, int zPerSet) {
    int z = blockIdx.z;
    int set = z / zPerSet;
    int zz = z % zPerSet;
    int bb = zz / nH, hh = zz % nH;

    const float* A  = (set == 0) ? A0 : (set == 1 ? A1 : A2);
    const float* Bm = (set == 0) ? W0 : (set == 1 ? W1 : W2);
    const float* bias = (set == 0) ? bias0 : (set == 1 ? bias1 : bias2);
    float* C = (set == 0) ? C0 : (set == 1 ? C1 : C2);
    A  += bb * sA + hh * hA;
    Bm += bb * sB + hh * hB;
    C  += bb * sC + hh * hC;

    extern __shared__ float dynsm[];
    float* Araw = dynsm;                          // [2][64][PADK]
    float* Braw = dynsm + 2 * 64 * PADK;          // nt: [2][32][PADN]; t: [2][64][PADK]
    float2* Asp = (float2*)(dynsm + RAW_FLOATS);  // [64][SPA]
    float2* Bsp = Asp + ASP_F2;                   // nt: [32][SPB]; t: [64][SPA]

    int tid = threadIdx.x;
    int lane = tid & 31, wid = tid >> 5;
    int wm = wid & 1, wn = wid >> 1;
    int l3 = lane & 3, l2 = lane >> 2;

    int bm = blockIdx.y * 64;
    int bn = blockIdx.x * 64;

    int ar = tid >> 2, ak = (tid & 3) * 4;
    int nbr = tid >> 4, nbc = (tid & 15) * 4;

    float acc[2][2][4] = {};

    int nk = K / 32;

    // prologue: chunks 0,1 -> raw stages 0,1
    #pragma unroll
    for (int p = 0; p < 2; p++) {
        int k0 = p * 32;
        float* As = Araw + p * 64 * PADK;
        cp16(&As[ar * PADK + ak],      A + (size_t)(bm + ar) * lda + k0 + ak);
        cp16(&As[ar * PADK + ak + 16], A + (size_t)(bm + ar) * lda + k0 + 16 + ak);
        if (TRANSB) {
            float* Bs = Braw + p * 64 * PADK;
            cp16(&Bs[ar * PADK + ak],      Bm + (size_t)(bn + ar) * ldb + k0 + ak);
            cp16(&Bs[ar * PADK + ak + 16], Bm + (size_t)(bn + ar) * ldb + k0 + 16 + ak);
        } else {
            float* Bs = Braw + p * 32 * PADN;
            cp16(&Bs[nbr * PADN + nbc],        Bm + (size_t)(k0 + nbr) * ldb + bn + nbc);
            cp16(&Bs[(nbr + 16) * PADN + nbc], Bm + (size_t)(k0 + nbr + 16) * ldb + bn + nbc);
        }
        CP_COMMIT();
    }

    for (int kt = 0; kt < nk; kt++) {
        CP_WAIT(1);
        __syncthreads();          // raw[kt&1] arrived; prior compute done (SP reusable)

        // cooperative split raw -> split planes (once per element)
        {
            const float* As = Araw + (kt & 1) * 64 * PADK;
            #pragma unroll
            for (int t = 0; t < 8; t++) {
                int e = tid + t * 256;            // 2048 elements
                int r = e >> 5, c = e & 31;
                Asp[r * SPA + c] = split2f(As[r * PADK + c]);
            }
            if (TRANSB) {
                const float* Bs = Braw + (kt & 1) * 64 * PADK;
                #pragma unroll
                for (int t = 0; t < 8; t++) {
                    int e = tid + t * 256;
                    int r = e >> 5, c = e & 31;
                    Bsp[r * SPA + c] = split2f(Bs[r * PADK + c]);
                }
            } else {
                const float* Bs = Braw + (kt & 1) * 32 * PADN;
                #pragma unroll
                for (int t = 0; t < 8; t++) {
                    int e = tid + t * 256;        // 32x64
                    int r = e >> 6, c = e & 63;
                    Bsp[r * SPB + c] = split2f(Bs[r * PADN + c]);
                }
            }
        }
        __syncthreads();          // splits visible; raw stage free for refill

        if (kt + 2 < nk) {
            int k0 = (kt + 2) * 32;
            float* As = Araw + (kt & 1) * 64 * PADK;
            cp16(&As[ar * PADK + ak],      A + (size_t)(bm + ar) * lda + k0 + ak);
            cp16(&As[ar * PADK + ak + 16], A + (size_t)(bm + ar) * lda + k0 + 16 + ak);
            if (TRANSB) {
                float* Bs = Braw + (kt & 1) * 64 * PADK;
                cp16(&Bs[ar * PADK + ak],      Bm + (size_t)(bn + ar) * ldb + k0 + ak);
                cp16(&Bs[ar * PADK + ak + 16], Bm + (size_t)(bn + ar) * ldb + k0 + 16 + ak);
            } else {
                float* Bs = Braw + (kt & 1) * 32 * PADN;
                cp16(&Bs[nbr * PADN + nbc],        Bm + (size_t)(k0 + nbr) * ldb + bn + nbc);
                cp16(&Bs[(nbr + 16) * PADN + nbc], Bm + (size_t)(k0 + nbr + 16) * ldb + bn + nbc);
            }
        }
        CP_COMMIT();

        // compute: pure LDS.64 + MMA
        #pragma unroll
        for (int ks = 0; ks < 32; ks += 8) {
            unsigned ah[2][4], al[2][4], bh[2][2], bl[2][2];
            #pragma unroll
            for (int i = 0; i < 2; i++) {
                int m0 = wm * 32 + i * 16;
                float2 v0 = Asp[(m0 + l2) * SPA + ks + l3];
                float2 v1 = Asp[(m0 + l2 + 8) * SPA + ks + l3];
                float2 v2 = Asp[(m0 + l2) * SPA + ks + l3 + 4];
                float2 v3 = Asp[(m0 + l2 + 8) * SPA + ks + l3 + 4];
                ah[i][0] = __float_as_uint(v0.x); al[i][0] = __float_as_uint(v0.y);
                ah[i][1] = __float_as_uint(v1.x); al[i][1] = __float_as_uint(v1.y);
                ah[i][2] = __float_as_uint(v2.x); al[i][2] = __float_as_uint(v2.y);
                ah[i][3] = __float_as_uint(v3.x); al[i][3] = __float_as_uint(v3.y);
            }
            #pragma unroll
            for (int j = 0; j < 2; j++) {
                int n0 = wn * 16 + j * 8;
                float2 b0, b1;
                if (TRANSB) {
                    b0 = Bsp[(n0 + l2) * SPA + ks + l3];
                    b1 = Bsp[(n0 + l2) * SPA + ks + l3 + 4];
                } else {
                    b0 = Bsp[(ks + l3) * SPB + n0 + l2];
                    b1 = Bsp[(ks + l3 + 4) * SPB + n0 + l2];
                }
                bh[j][0] = __float_as_uint(b0.x); bl[j][0] = __float_as_uint(b0.y);
                bh[j][1] = __float_as_uint(b1.x); bl[j][1] = __float_as_uint(b1.y);
            }
            #pragma unroll
            for (int i = 0; i < 2; i++)
                #pragma unroll
                for (int j = 0; j < 2; j++)
                    mma_tf32(acc[i][j], ah[i], bh[j]);
            #pragma unroll
            for (int i = 0; i < 2; i++)
                #pragma unroll
                for (int j = 0; j < 2; j++)
                    mma_tf32(acc[i][j], ah[i], bl[j]);
            #pragma unroll
            for (int i = 0; i < 2; i++)
                #pragma unroll
                for (int j = 0; j < 2; j++)
                    mma_tf32(acc[i][j], al[i], bh[j]);
        }
    }

    // epilogue
    #pragma unroll
    for (int i = 0; i < 2; i++) {
        #pragma unroll
        for (int j = 0; j < 2; j++) {
            int rg = bm + wm * 32 + i * 16 + l2;
            int cg = bn + wn * 16 + j * 8 + 2 * l3;
            float bv0 = bias ? bias[cg] : 0.0f;
            float bv1 = bias ? bias[cg + 1] : 0.0f;
            float v0 = acc[i][j][0] + bv0, v1 = acc[i][j][1] + bv1;
            float v2 = acc[i][j][2] + bv0, v3 = acc[i][j][3] + bv1;
            if (act) { v0 = gelu_f(v0); v1 = gelu_f(v1); v2 = gelu_f(v2); v3 = gelu_f(v3); }
            *(float2*)(C + (size_t)rg * ldc + cg) = make_float2(v0, v1);
            *(float2*)(C + (size_t)(rg + 8) * ldc + cg) = make_float2(v2, v3);
        }
    }
}

#define GEMM_SMEM_NT ((RAW_FLOATS + 2 * (ASP_F2 + 32 * SPB)) * 4)
#define GEMM_SMEM_T  ((RAW_FLOATS + 2 * (ASP_F2 + 64 * SPA)) * 4)

// ---------------- fused attention: 32-row Q tiles, pre-split Q/P planes ------
#define APAD 132
#define QR 32
__global__ __launch_bounds__(256)
void fused_attn(const float* __restrict__ Q, const float* __restrict__ K,
                const float* __restrict__ V, float* __restrict__ O) {
    extern __shared__ float dyn[];
    float*  Qraw = dyn;
    float2* Qsp  = (float2*)(dyn + QR * APAD);
    float*  Kbuf = dyn + QR * APAD * 3;
    __shared__ float redM[QR][8];
    __shared__ float redS[QR][8];

    int bz = blockIdx.y;
    int bb = bz >> 2, h = bz & 3;
    int qbase = blockIdx.x * QR;

    int tid = threadIdx.x;
    int lane = tid & 31, wn = tid >> 5;
    int l3 = lane & 3, l2 = lane >> 2;

    const float* Qg = Q + ((size_t)bb * T + qbase) * D + h * DK;
    const float* Kg = K + ((size_t)bb * T) * D + h * DK;
    const float* Vg = V + ((size_t)bb * T) * D + h * DK;

    #pragma unroll
    for (int t = 0; t < 4; t++) {
        int idx = tid + t * 256;
        int r = idx >> 5, c = (idx & 31) * 4;
        cp16(&Qraw[r * APAD + c], Qg + (size_t)r * D + c);
    }
    CP_COMMIT();
    #pragma unroll
    for (int t = 0; t < 16; t++) {
        int idx = tid + t * 256;
        int r = idx >> 5, c = (idx & 31) * 4;
        cp16(&Kbuf[r * APAD + c], Kg + (size_t)r * D + c);
    }
    CP_COMMIT();
    CP_WAIT(0);
    __syncthreads();

    #pragma unroll
    for (int t = 0; t < 16; t++) {
        int idx = tid + t * 256;
        int r = idx >> 7, c = idx & 127;
        Qsp[r * APAD + c] = split2f(Qraw[r * APAD + c]);
    }
    __syncthreads();

    float acc[2][2][4] = {};
    #pragma unroll 4
    for (int ks = 0; ks < DK; ks += 8) {
        unsigned ah[2][4], al[2][4], bh[2][2], bl[2][2];
        #pragma unroll
        for (int i = 0; i < 2; i++) {
            int m0 = i * 16;
            float2 v0 = Qsp[(m0 + l2) * APAD + ks + l3];
            float2 v1 = Qsp[(m0 + l2 + 8) * APAD + ks + l3];
            float2 v2 = Qsp[(m0 + l2) * APAD + ks + l3 + 4];
            float2 v3 = Qsp[(m0 + l2 + 8) * APAD + ks + l3 + 4];
            ah[i][0] = __float_as_uint(v0.x); al[i][0] = __float_as_uint(v0.y);
            ah[i][1] = __float_as_uint(v1.x); al[i][1] = __float_as_uint(v1.y);
            ah[i][2] = __float_as_uint(v2.x); al[i][2] = __float_as_uint(v2.y);
            ah[i][3] = __float_as_uint(v3.x); al[i][3] = __float_as_uint(v3.y);
        }
        #pragma unroll
        for (int j = 0; j < 2; j++) {
            int n0 = wn * 16 + j * 8;
            split2(Kbuf[(n0 + l2) * APAD + ks + l3],     bh[j][0], bl[j][0]);
            split2(Kbuf[(n0 + l2) * APAD + ks + l3 + 4], bh[j][1], bl[j][1]);
        }
        #pragma unroll
        for (int i = 0; i < 2; i++)
            #pragma unroll
            for (int j = 0; j < 2; j++)
                mma_tf32(acc[i][j], ah[i], bh[j]);
        #pragma unroll
        for (int i = 0; i < 2; i++)
            #pragma unroll
            for (int j = 0; j < 2; j++)
                mma_tf32(acc[i][j], ah[i], bl[j]);
        #pragma unroll
        for (int i = 0; i < 2; i++)
            #pragma unroll
            for (int j = 0; j < 2; j++)
                mma_tf32(acc[i][j], al[i], bh[j]);
    }
    __syncthreads();

    #pragma unroll
    for (int t = 0; t < 16; t++) {
        int idx = tid + t * 256;
        int r = idx >> 5, c = (idx & 31) * 4;
        cp16(&Kbuf[r * APAD + c], Vg + (size_t)r * D + c);
    }
    CP_COMMIT();

    const float sc = 0.08838834764831845f;
    #pragma unroll
    for (int i = 0; i < 2; i++)
        #pragma unroll
        for (int j = 0; j < 2; j++)
            #pragma unroll
            for (int q = 0; q < 4; q++) acc[i][j][q] *= sc;

    #pragma unroll
    for (int i = 0; i < 2; i++)
        #pragma unroll
        for (int hf = 0; hf < 2; hf++) {
            int row = i * 16 + l2 + hf * 8;
            float m = fmaxf(fmaxf(acc[i][0][2 * hf], acc[i][0][2 * hf + 1]),
                            fmaxf(acc[i][1][2 * hf], acc[i][1][2 * hf + 1]));
            m = fmaxf(m, __shfl_xor_sync(0xffffffff, m, 1));
            m = fmaxf(m, __shfl_xor_sync(0xffffffff, m, 2));
            if (l3 == 0) redM[row][wn] = m;
        }
    __syncthreads();
    #pragma unroll
    for (int i = 0; i < 2; i++)
        #pragma unroll
        for (int hf = 0; hf < 2; hf++) {
            int row = i * 16 + l2 + hf * 8;
            float m = redM[row][0];
            #pragma unroll
            for (int w2 = 1; w2 < 8; w2++) m = fmaxf(m, redM[row][w2]);
            float s = 0.0f;
            #pragma unroll
            for (int j = 0; j < 2; j++) {
                acc[i][j][2 * hf]     = expf(acc[i][j][2 * hf] - m);
                acc[i][j][2 * hf + 1] = expf(acc[i][j][2 * hf + 1] - m);
                s += acc[i][j][2 * hf] + acc[i][j][2 * hf + 1];
            }
            s += __shfl_xor_sync(0xffffffff, s, 1);
            s += __shfl_xor_sync(0xffffffff, s, 2);
            if (l3 == 0) redS[row][wn] = s;
        }
    __syncthreads();
    #pragma unroll
    for (int i = 0; i < 2; i++)
        #pragma unroll
        for (int hf = 0; hf < 2; hf++) {
            int row = i * 16 + l2 + hf * 8;
            float ssum = redS[row][0];
            #pragma unroll
            for (int w2 = 1; w2 < 8; w2++) ssum += redS[row][w2];
            float inv = 1.0f / ssum;
            #pragma unroll
            for (int j = 0; j < 2; j++) {
                int col = wn * 16 + j * 8 + 2 * l3;
                Qsp[row * APAD + col]     = split2f(acc[i][j][2 * hf] * inv);
                Qsp[row * APAD + col + 1] = split2f(acc[i][j][2 * hf + 1] * inv);
            }
        }
    CP_WAIT(0);
    __syncthreads();

    float out[2][2][4] = {};
    #pragma unroll 4
    for (int ks = 0; ks < T; ks += 8) {
        unsigned ah[2][4], al[2][4], bh[2][2], bl[2][2];
        #pragma unroll
        for (int i = 0; i < 2; i++) {
            int m0 = i * 16;
            float2 v0 = Qsp[(m0 + l2) * APAD + ks + l3];
            float2 v1 = Qsp[(m0 + l2 + 8) * APAD + ks + l3];
            float2 v2 = Qsp[(m0 + l2) * APAD + ks + l3 + 4];
            float2 v3 = Qsp[(m0 + l2 + 8) * APAD + ks + l3 + 4];
            ah[i][0] = __float_as_uint(v0.x); al[i][0] = __float_as_uint(v0.y);
            ah[i][1] = __float_as_uint(v1.x); al[i][1] = __float_as_uint(v1.y);
            ah[i][2] = __float_as_uint(v2.x); al[i][2] = __float_as_uint(v2.y);
            ah[i][3] = __float_as_uint(v3.x); al[i][3] = __float_as_uint(v3.y);
        }
        #pragma unroll
        for (int j = 0; j < 2; j++) {
            int n0 = wn * 16 + j * 8;
            split2(Kbuf[(ks + l3) * APAD + n0 + l2],     bh[j][0], bl[j][0]);
            split2(Kbuf[(ks + l3 + 4) * APAD + n0 + l2], bh[j][1], bl[j][1]);
        }
        #pragma unroll
        for (int i = 0; i < 2; i++)
            #pragma unroll
            for (int j = 0; j < 2; j++)
                mma_tf32(out[i][j], ah[i], bh[j]);
        #pragma unroll
        for (int i = 0; i < 2; i++)
            #pragma unroll
            for (int j = 0; j < 2; j++)
                mma_tf32(out[i][j], ah[i], bl[j]);
        #pragma unroll
        for (int i = 0; i < 2; i++)
            #pragma unroll
            for (int j = 0; j < 2; j++)
                mma_tf32(out[i][j], al[i], bh[j]);
    }

    float* Og = O + ((size_t)bb * T + qbase) * D + h * DK;
    #pragma unroll
    for (int i = 0; i < 2; i++)
        #pragma unroll
        for (int j = 0; j < 2; j++) {
            int r = i * 16 + l2;
            int c = wn * 16 + j * 8 + 2 * l3;
            *(float2*)(Og + (size_t)r * D + c) = make_float2(out[i][j][0], out[i][j][1]);
            *(float2*)(Og + (size_t)(r + 8) * D + c) = make_float2(out[i][j][2], out[i][j][3]);
        }
}

// ---------------- warp helpers ----------------------------------------------
__device__ __forceinline__ float warp_sum(float v) {
    #pragma unroll
    for (int o = 16; o > 0; o >>= 1) v += __shfl_xor_sync(0xffffffff, v, o);
    return v;
}
__device__ __forceinline__ float warp_max(float v) {
    #pragma unroll
    for (int o = 16; o > 0; o >>= 1) v = fmaxf(v, __shfl_xor_sync(0xffffffff, v, o));
    return v;
}

// ---------------- LayerNorm kernels ------------------------------------------
__global__ void add_pos_ln_kernel(const float* __restrict__ qe, const float* __restrict__ ae,
                                  const float* __restrict__ pos,
                                  const float* __restrict__ w, const float* __restrict__ b,
                                  float* __restrict__ out) {
    int row = blockIdx.x, tid = threadIdx.x;
    int lane = tid & 31, wd = tid >> 5;
    __shared__ float p1[4], p2[4];

    const float* src = (row < 512) ? (qe + (size_t)row * D) : (ae + (size_t)(row - 512) * D);
    float4 xv = ((const float4*)src)[tid];
    float4 pv = ((const float4*)(pos + (size_t)(row % T) * D))[tid];
    float4 v = make_float4(xv.x + pv.x, xv.y + pv.y, xv.z + pv.z, xv.w + pv.w);

    float s = warp_sum(v.x + v.y + v.z + v.w);
    if (lane == 0) p1[wd] = s;
    __syncthreads();
    float mean = (p1[0] + p1[1] + p1[2] + p1[3]) * (1.0f / D);
    float4 d = make_float4(v.x - mean, v.y - mean, v.z - mean, v.w - mean);
    float q = warp_sum(d.x * d.x + d.y * d.y + d.z * d.z + d.w * d.w);
    if (lane == 0) p2[wd] = q;
    __syncthreads();
    float inv = rsqrtf((p2[0] + p2[1] + p2[2] + p2[3]) * (1.0f / D) + 1e-12f);

    float4 wv = ((const float4*)w)[tid];
    float4 bv = ((const float4*)b)[tid];
    ((float4*)(out + (size_t)row * D))[tid] =
        make_float4(wv.x * d.x * inv + bv.x, wv.y * d.y * inv + bv.y,
                    wv.z * d.z * inv + bv.z, wv.w * d.w * inv + bv.w);
}

__global__ void residual_ln2_kernel(float* __restrict__ x, const float* __restrict__ y0,
                                    const float* __restrict__ y1,
                                    float* __restrict__ out,
                                    const float* __restrict__ w, const float* __restrict__ b) {
    int row = blockIdx.x, tid = threadIdx.x;
    int lane = tid & 31, wd = tid >> 5;
    __shared__ float p1[4], p2[4];

    float4 xv = ((const float4*)(x + (size_t)row * D))[tid];
    float4 y0v = ((const float4*)(y0 + (size_t)row * D))[tid];
    float4 v = make_float4(xv.x + y0v.x, xv.y + y0v.y, xv.z + y0v.z, xv.w + y0v.w);
    if (y1) {
        float4 y1v = ((const float4*)(y1 + (size_t)row * D))[tid];
        v.x += y1v.x; v.y += y1v.y; v.z += y1v.z; v.w += y1v.w;
    }
    ((float4*)(x + (size_t)row * D))[tid] = v;

    float s = warp_sum(v.x + v.y + v.z + v.w);
    if (lane == 0) p1[wd] = s;
    __syncthreads();
    float mean = (p1[0] + p1[1] + p1[2] + p1[3]) * (1.0f / D);
    float4 d = make_float4(v.x - mean, v.y - mean, v.z - mean, v.w - mean);
    float q = warp_sum(d.x * d.x + d.y * d.y + d.z * d.z + d.w * d.w);
    if (lane == 0) p2[wd] = q;
    __syncthreads();
    float inv = rsqrtf((p2[0] + p2[1] + p2[2] + p2[3]) * (1.0f / D) + 1e-12f);

    float4 wv = ((const float4*)w)[tid];
    float4 bv = ((const float4*)b)[tid];
    ((float4*)(out + (size_t)row * D))[tid] =
        make_float4(wv.x * d.x * inv + bv.x, wv.y * d.y * inv + bv.y,
                    wv.z * d.z * inv + bv.z, wv.w * d.w * inv + bv.w);
}

// ---------------- sim head helpers ------------------------------------------
__global__ void edot_kernel(const float* __restrict__ X, const float* __restrict__ E,
                            float* __restrict__ out) {
    int row = blockIdx.x;
    int tid = threadIdx.x;
    __shared__ float red[NC * 256];
    float acc[NC] = {};
    for (int d = tid; d < D; d += 256) {
        float x = X[(size_t)row * D + d];
        #pragma unroll
        for (int c = 0; c < NC; c++) acc[c] += x * E[(size_t)c * D + d];
    }
    #pragma unroll
    for (int c = 0; c < NC; c++) red[c * 256 + tid] = acc[c];
    __syncthreads();
    for (int off = 128; off > 0; off >>= 1) {
        if (tid < off) {
            #pragma unroll
            for (int c = 0; c < NC; c++) red[c * 256 + tid] += red[c * 256 + tid + off];
        }
        __syncthreads();
    }
    if (tid < NC) out[(size_t)row * NC + tid] = red[tid * 256];
}

__global__ void gram_kernel(const float* __restrict__ E, float* __restrict__ G) {
    int i = threadIdx.x;
    if (i < NC * NC) {
        int c = i / NC, c2 = i % NC;
        float s = 0.0f;
        for (int d = 0; d < D; d++) s += E[(size_t)c * D + d] * E[(size_t)c2 * D + d];
        G[i] = s;
    }
}

__global__ void sim_attn_kernel(const float* __restrict__ QK, const float* __restrict__ QK2,
                                const float* __restrict__ qa,
                                const float* __restrict__ aq, const float* __restrict__ Eq,
                                const float* __restrict__ Ek, const float* __restrict__ G,
                                float* __restrict__ P, float* __restrict__ Wout) {
    int t = blockIdx.x, b = blockIdx.y;
    int s = threadIdx.x;
    int lane = s & 31, wd = s >> 5;
    __shared__ float g[NC * NC];
    __shared__ float part[4];
    __shared__ float pv[T];
    if (s < NC * NC) g[s] = G[s];
    __syncthreads();

    float f1[NC], f2[NC];
    const float* r1 = qa + (((size_t)b * T + t) * T + s) * NC;
    const float* r2 = aq + (((size_t)b * T + s) * T + t) * NC;
    #pragma unroll
    for (int c = 0; c < NC; c++) { f1[c] = r1[c]; f2[c] = r2[c]; }

    size_t qkidx = ((size_t)b * T + t) * T + s;
    float sc = QK[qkidx] + QK2[qkidx];
    const float* eq = Eq + ((size_t)b * T + t) * NC;
    const float* ek = Ek + ((size_t)b * T + s) * NC;
    #pragma unroll
    for (int c = 0; c < NC; c++) sc += f1[c] * ek[c] + f2[c] * eq[c];
    #pragma unroll
    for (int c = 0; c < NC; c++)
        #pragma unroll
        for (int c2 = 0; c2 < NC; c2++)
            sc += f1[c] * g[c * NC + c2] * f2[c2];

    float m = warp_max(sc);
    if (lane == 0) part[wd] = m;
    __syncthreads();
    float m1 = fmaxf(fmaxf(part[0], part[1]), fmaxf(part[2], part[3]));
    float e1 = expf(sc - m1);
    float ssum = warp_sum(e1);
    if (lane == 0) part[wd] = ssum;
    __syncthreads();
    float p = e1 / (part[0] + part[1] + part[2] + part[3]);

    float l = 1000.0f * p;
    m = warp_max(l);
    __syncthreads();
    if (lane == 0) part[wd] = m;
    __syncthreads();
    float m2 = fmaxf(fmaxf(part[0], part[1]), fmaxf(part[2], part[3]));
    float e2 = expf(l - m2);
    ssum = warp_sum(e2);
    __syncthreads();
    if (lane == 0) part[wd] = ssum;
    __syncthreads();
    float p2 = e2 / (part[0] + part[1] + part[2] + part[3]);
    p2 = fminf(fmaxf(p2, 0.0f), 1.0f);

    P[((size_t)b * T + t) * T + s] = p2;
    pv[s] = p2;
    __syncthreads();

    #pragma unroll
    for (int c = 0; c < NC; c++) {
        float v = warp_sum(pv[s] * f2[c]);
        __syncthreads();
        if (lane == 0) part[wd] = v;
        __syncthreads();
        if (s == 0) Wout[((size_t)b * T + t) * NC + c] = part[0] + part[1] + part[2] + part[3];
    }
}

__global__ void final_kernel(const float* __restrict__ pk, const float* __restrict__ pk2,
                             const float* __restrict__ Wm,
                             const float* __restrict__ E, const float* __restrict__ clsw,
                             const float* __restrict__ clsb, float* __restrict__ out) {
    int b = blockIdx.x;
    int d = threadIdx.x;
    __shared__ float wm[NC];
    __shared__ float red[512];

    if (d < NC) {
        float s = 0.0f;
        for (int t = 0; t < T; t++) s += Wm[((size_t)b * T + t) * NC + d];
        wm[d] = s * (1.0f / T);
    }
    __syncthreads();

    float s = 0.0f;
    for (int t = 0; t < T; t++)
        s += pk[((size_t)b * T + t) * D + d] + pk2[((size_t)b * T + t) * D + d];
    s *= (1.0f / T);
    #pragma unroll
    for (int c = 0; c < NC; c++) s += wm[c] * E[(size_t)c * D + d];

    for (int j = 0; j < 3; j++) {
        red[d] = s * clsw[(size_t)d * 3 + j];
        __syncthreads();
        for (int off = 256; off > 0; off >>= 1) { if (d < off) red[d] += red[d + off]; __syncthreads(); }
        if (d == 0) out[b * 3 + j] = red[0] + clsb[j];
        __syncthreads();
    }
}

// ---------------- host orchestration ----------------------------------------
static inline void g_launch(int transB,
                            const float* A0, const float* A1, const float* A2,
                            const float* W0, const float* W1, const float* W2,
                            const float* b0, const float* b1, const float* b2,
                            float* C0, float* C1, float* C2,
                            int M, int N, int K, int lda, int ldb, int ldc,
                            int act, int nH,
                            long long sA, long long hA, long long sB, long long hB,
                            long long sC, long long hC, int zPerSet, int nz) {
    dim3 grid(N / 64, M / 64, nz);
    if (transB)
        gemm_tf32<1><<<grid, 256, GEMM_SMEM_T>>>(A0, A1, A2, W0, W1, W2, b0, b1, b2, C0, C1, C2,
                                                 M, N, K, lda, ldb, ldc, act, nH,
                                                 sA, hA, sB, hB, sC, hC, zPerSet);
    else
        gemm_tf32<0><<<grid, 256, GEMM_SMEM_NT>>>(A0, A1, A2, W0, W1, W2, b0, b1, b2, C0, C1, C2,
                                                  M, N, K, lda, ldb, ldc, act, nH,
                                                  sA, hA, sB, hB, sC, hC, zPerSet);
}

extern "C" void kernel_launch(void* const* d_in, const int* in_sizes, int n_in,
                              void* d_out, int out_size) {
    const float* q_emb   = (const float*)d_in[0];
    const float* a_emb   = (const float*)d_in[1];
    const float* qa_rel  = (const float*)d_in[2];
    const float* aq_rel  = (const float*)d_in[3];
    const float* conceptE= (const float*)d_in[4];
    const float* pos_emb = (const float*)d_in[5];
    const float* pe_w    = (const float*)d_in[6];
    const float* pe_b    = (const float*)d_in[7];
    const float* Wq      = (const float*)d_in[8];
    const float* bq      = (const float*)d_in[9];
    const float* Wk      = (const float*)d_in[10];
    const float* bk      = (const float*)d_in[11];
    const float* Wv      = (const float*)d_in[12];
    const float* bv      = (const float*)d_in[13];
    const float* Wo      = (const float*)d_in[14];
    const float* bo      = (const float*)d_in[15];
    const float* ff1w    = (const float*)d_in[16];
    const float* ff1b    = (const float*)d_in[17];
    const float* ff2w    = (const float*)d_in[18];
    const float* ff2b    = (const float*)d_in[19];
    const float* lninw   = (const float*)d_in[20];
    const float* lninb   = (const float*)d_in[21];
    const float* lnoutw  = (const float*)d_in[22];
    const float* lnoutb  = (const float*)d_in[23];
    const float* simWq   = (const float*)d_in[24];
    const float* simbq   = (const float*)d_in[25];
    const float* simWk   = (const float*)d_in[26];
    const float* simbk   = (const float*)d_in[27];
    const float* clsw    = (const float*)d_in[28];
    const float* clsb    = (const float*)d_in[29];
    float* out = (float*)d_out;

    float* base = nullptr;
    cudaGetSymbolAddress((void**)&base, g_scratch);

    float* X   = base + OFF_X;
    float* Qb  = base + OFF_Q;
    float* Kb  = base + OFF_K;
    float* Vb  = base + OFF_V;
    float* T0  = base + OFF_T0;
    float* T1b = base + OFF_T1;
    float* T2b = base + OFF_T2;
    float* Hb  = base + OFF_H;
    float* FFN = base + OFF_FFN;
    float* QKb = base + OFF_QK;
    float* QK2b= base + OFF_QK2;
    float* Pb  = base + OFF_P;
    float* EQb = base + OFF_EQ;
    float* EKb = base + OFF_EK;
    float* Gb  = base + OFF_G;
    float* Wb  = base + OFF_W;
    float* PKb = base + OFF_PK;
    float* PK2b= base + OFF_PK2;

    static const int ATTN_SMEM = (QR * APAD * 3 + 128 * APAD) * 4;
    cudaFuncSetAttribute(fused_attn, cudaFuncAttributeMaxDynamicSharedMemorySize, ATTN_SMEM);
    cudaFuncSetAttribute(gemm_tf32<0>, cudaFuncAttributeMaxDynamicSharedMemorySize, GEMM_SMEM_NT);
    cudaFuncSetAttribute(gemm_tf32<1>, cudaFuncAttributeMaxDynamicSharedMemorySize, GEMM_SMEM_T);

    add_pos_ln_kernel<<<M2, 128>>>(q_emb, a_emb, pos_emb, pe_w, pe_b, X);

    for (int i = 0; i < NL; i++) {
        const float* wq = Wq + (size_t)i * D * D;
        const float* wk = Wk + (size_t)i * D * D;
        const float* wv = Wv + (size_t)i * D * D;
        const float* wo = Wo + (size_t)i * D * D;

        g_launch(0, X, X, X, wq, wk, wv,
                 bq + (size_t)i * D, bk + (size_t)i * D, bv + (size_t)i * D,
                 Qb, Kb, Vb,
                 M2, D, D, D, D, D, 0, 1, 0, 0, 0, 0, 0, 0, 1, 3);

        fused_attn<<<dim3(4, 32), 256, ATTN_SMEM>>>(Qb, Kb, Vb, T0);

        g_launch(0, T0, T0 + 256, 0, wo, wo + (size_t)256 * D, 0,
                 bo + (size_t)i * D, 0, 0, T1b, T2b, 0,
                 M2, D, 256, D, D, D, 0, 1, 0, 0, 0, 0, 0, 0, 1, 2);

        residual_ln2_kernel<<<M2, 128>>>(X, T1b, T2b, Hb,
                                         lninw + (size_t)i * D, lninb + (size_t)i * D);

        g_launch(0, Hb, 0, 0, ff1w + (size_t)i * D * DFF, 0, 0, ff1b + (size_t)i * DFF, 0, 0, FFN, 0, 0,
                 M2, DFF, D, D, DFF, DFF, 1, 1, 0, 0, 0, 0, 0, 0, 1, 1);

        g_launch(0, FFN, FFN + 1024, 0,
                 ff2w + (size_t)i * DFF * D, ff2w + (size_t)i * DFF * D + (size_t)1024 * D, 0,
                 ff2b + (size_t)i * D, 0, 0, T1b, T2b, 0,
                 M2, D, 1024, DFF, D, D, 0, 1, 0, 0, 0, 0, 0, 0, 1, 2);

        residual_ln2_kernel<<<M2, 128>>>(X, T1b, T2b, X,
                                         lnoutw + (size_t)i * D, lnoutb + (size_t)i * D);
    }

    // --- sim head ---
    g_launch(0, X, X + (size_t)(M2 / 2) * D, 0, simWq, simWk, 0, simbq, simbk, 0, Qb, Kb, 0,
             M2 / 2, D, D, D, D, D, 0, 1, 0, 0, 0, 0, 0, 0, 1, 2);

    edot_kernel<<<M2 / 2, 256>>>(Qb, conceptE, EQb);
    edot_kernel<<<M2 / 2, 256>>>(Kb, conceptE, EKb);
    gram_kernel<<<1, 32>>>(conceptE, Gb);

    g_launch(1, Qb, Qb + 256, 0, Kb, Kb + 256, 0, 0, 0, 0, QKb, QK2b, 0,
             T, T, 256, D, D, T, 0, 1,
             (long long)T * D, 0, (long long)T * D, 0, (long long)T * T, 0, 4, 8);

    sim_attn_kernel<<<dim3(T, Bb), 128>>>(QKb, QK2b, qa_rel, aq_rel, EQb, EKb, Gb, Pb, Wb);

    g_launch(0, Pb, Pb + 64, 0, Kb, Kb + (size_t)64 * D, 0, 0, 0, 0, PKb, PK2b, 0,
             T, D, 64, T, D, D, 0, 1,
             (long long)T * T, 0, (long long)T * D, 0, (long long)T * D, 0, 4, 8);

    final_kernel<<<Bb, 512>>>(PKb, PK2b, Wb, conceptE, clsw, clsb, out);
}

// round 14
// speedup vs baseline: 1.4367x; 1.4367x over previous
#include <cuda_runtime.h>
#include <cuda_bf16.h>
#include <math.h>

// Problem constants
#define Bb   4
#define T    128
#define D    512
#define Hh   4
#define DK   128
#define NL   4
#define DFF  2048
#define NC   5

#define M2   1024
#define ND   (M2*D)

// ---------------- scratch ----------------------------------------------------
#define OFF_X   0
#define OFF_Q   (1*ND)
#define OFF_K   (2*ND)
#define OFF_V   (3*ND)
#define OFF_T0  (4*ND)
#define OFF_TP  (5*ND)              // 4 contiguous split-K partials: 5..9 ND
#define OFF_H   (9*ND)
#define OFF_FFN (10*ND)             // M2*DFF = 4*ND -> ..14 ND
#define OFF_QK  (14*ND)
#define OFF_P   (OFF_QK + 65536)
#define OFF_EQ  (OFF_P + 65536)
#define OFF_EK  (OFF_EQ + 2560)
#define OFF_G   (OFF_EK + 2560)
#define OFF_W   (OFF_G + 32)
#define OFF_PK  (OFF_W + 2560)
#define OFF_QK2 (OFF_PK + 262144)
#define OFF_PK2 (OFF_QK2 + 65536)
#define SCRATCH_TOTAL (OFF_PK2 + 262144)

__device__ float g_scratch[SCRATCH_TOTAL];

__device__ __forceinline__ float gelu_f(float x) {
    return 0.5f * x * (1.0f + erff(x * 0.7071067811865475f));
}

// ---------------- tf32 / mma / cp.async helpers ------------------------------
__device__ __forceinline__ unsigned f2tf32(float x) {
    unsigned r;
    asm("cvt.rna.tf32.f32 %0, %1;" : "=r"(r) : "f"(x));
    return r;
}
__device__ __forceinline__ void split2(float x, unsigned& hi, unsigned& lo) {
    hi = f2tf32(x);
    lo = f2tf32(x - __uint_as_float(hi));
}
__device__ __forceinline__ float2 split2f(float x) {
    unsigned h, l;
    split2(x, h, l);
    return make_float2(__uint_as_float(h), __uint_as_float(l));
}
__device__ __forceinline__ void mma_tf32(float* c, const unsigned* a, const unsigned* b) {
    asm volatile(
        "mma.sync.aligned.m16n8k8.row.col.f32.tf32.tf32.f32 "
        "{%0,%1,%2,%3},{%4,%5,%6,%7},{%8,%9},{%0,%1,%2,%3};"
        : "+f"(c[0]), "+f"(c[1]), "+f"(c[2]), "+f"(c[3])
        : "r"(a[0]), "r"(a[1]), "r"(a[2]), "r"(a[3]), "r"(b[0]), "r"(b[1]));
}
__device__ __forceinline__ void cp16(void* s, const void* g) {
    unsigned sa = (unsigned)__cvta_generic_to_shared(s);
    asm volatile("cp.async.cg.shared.global [%0], [%1], 16;\n" :: "r"(sa), "l"(g) : "memory");
}
#define CP_COMMIT() asm volatile("cp.async.commit_group;\n" ::: "memory")
#define CP_WAIT(n)  asm volatile("cp.async.wait_group %0;\n" :: "n"(n) : "memory")

// ---------------- 64x64 3xTF32 GEMM (sim head), BK=32, 3-stage ---------------
#define PADK 36
#define PADN 72

template<int TRANSB>
__global__ __launch_bounds__(256, 2)
void gemm_tf32(const float* __restrict__ A0, const float* __restrict__ A1, const float* __restrict__ A2,
               const float* __restrict__ W0, const float* __restrict__ W1, const float* __restrict__ W2,
               const float* __restrict__ bias0, const float* __restrict__ bias1, const float* __restrict__ bias2,
               float* __restrict__ C0, float* __restrict__ C1, float* __restrict__ C2,
               int M, int N, int K, int lda, int ldb, int ldc,
               int act, int nH,
               long long sA, long long hA, long long sB, long long hB,
               long long sC, long long hC, int zPerSet) {
    int z = blockIdx.z;
    int set = z / zPerSet;
    int zz = z % zPerSet;
    int bb = zz / nH, hh = zz % nH;

    const float* A  = (set == 0) ? A0 : (set == 1 ? A1 : A2);
    const float* Bm = (set == 0) ? W0 : (set == 1 ? W1 : W2);
    const float* bias = (set == 0) ? bias0 : (set == 1 ? bias1 : bias2);
    float* C = (set == 0) ? C0 : (set == 1 ? C1 : C2);
    A  += bb * sA + hh * hA;
    Bm += bb * sB + hh * hB;
    C  += bb * sC + hh * hC;

    __shared__ float As[3][64][PADK];
    constexpr int BR = TRANSB ? 64 : 32;
    constexpr int BC = TRANSB ? PADK : PADN;
    __shared__ float Bs[3][BR][BC];

    int tid = threadIdx.x;
    int lane = tid & 31, wid = tid >> 5;
    int wm = wid & 1, wn = wid >> 1;
    int l3 = lane & 3, l2 = lane >> 2;

    int bm = blockIdx.y * 64;
    int bn = blockIdx.x * 64;

    int ar = tid >> 2, ak = (tid & 3) * 4;
    int nbr = tid >> 4, nbc = (tid & 15) * 4;

    float acc[2][2][4] = {};

    int nk = K / 32;

    #pragma unroll
    for (int p = 0; p < 2; p++) {
        int k0 = p * 32;
        cp16(&As[p][ar][ak],      A + (size_t)(bm + ar) * lda + k0 + ak);
        cp16(&As[p][ar][ak + 16], A + (size_t)(bm + ar) * lda + k0 + 16 + ak);
        if (TRANSB) {
            cp16(&Bs[p][ar][ak],      Bm + (size_t)(bn + ar) * ldb + k0 + ak);
            cp16(&Bs[p][ar][ak + 16], Bm + (size_t)(bn + ar) * ldb + k0 + 16 + ak);
        } else {
            cp16(&Bs[p][nbr][nbc],      Bm + (size_t)(k0 + nbr) * ldb + bn + nbc);
            cp16(&Bs[p][nbr + 16][nbc], Bm + (size_t)(k0 + nbr + 16) * ldb + bn + nbc);
        }
        CP_COMMIT();
    }

    for (int kt = 0; kt < nk; kt++) {
        CP_WAIT(1);
        __syncthreads();
        int st = kt % 3;
        if (kt + 2 < nk) {
            int ns = (kt + 2) % 3;
            int k0 = (kt + 2) * 32;
            cp16(&As[ns][ar][ak],      A + (size_t)(bm + ar) * lda + k0 + ak);
            cp16(&As[ns][ar][ak + 16], A + (size_t)(bm + ar) * lda + k0 + 16 + ak);
            if (TRANSB) {
                cp16(&Bs[ns][ar][ak],      Bm + (size_t)(bn + ar) * ldb + k0 + ak);
                cp16(&Bs[ns][ar][ak + 16], Bm + (size_t)(bn + ar) * ldb + k0 + 16 + ak);
            } else {
                cp16(&Bs[ns][nbr][nbc],      Bm + (size_t)(k0 + nbr) * ldb + bn + nbc);
                cp16(&Bs[ns][nbr + 16][nbc], Bm + (size_t)(k0 + nbr + 16) * ldb + bn + nbc);
            }
        }
        CP_COMMIT();

        #pragma unroll
        for (int ks = 0; ks < 32; ks += 8) {
            unsigned ah[2][4], al[2][4], bh[2][2], bl[2][2];
            #pragma unroll
            for (int i = 0; i < 2; i++) {
                int m0 = wm * 32 + i * 16;
                split2(As[st][m0 + l2][ks + l3],         ah[i][0], al[i][0]);
                split2(As[st][m0 + l2 + 8][ks + l3],     ah[i][1], al[i][1]);
                split2(As[st][m0 + l2][ks + l3 + 4],     ah[i][2], al[i][2]);
                split2(As[st][m0 + l2 + 8][ks + l3 + 4], ah[i][3], al[i][3]);
            }
            #pragma unroll
            for (int j = 0; j < 2; j++) {
                int n0 = wn * 16 + j * 8;
                if (TRANSB) {
                    split2(Bs[st][n0 + l2][ks + l3],     bh[j][0], bl[j][0]);
                    split2(Bs[st][n0 + l2][ks + l3 + 4], bh[j][1], bl[j][1]);
                } else {
                    split2(Bs[st][ks + l3][n0 + l2],     bh[j][0], bl[j][0]);
                    split2(Bs[st][ks + l3 + 4][n0 + l2], bh[j][1], bl[j][1]);
                }
            }
            #pragma unroll
            for (int i = 0; i < 2; i++)
                #pragma unroll
                for (int j = 0; j < 2; j++)
                    mma_tf32(acc[i][j], ah[i], bh[j]);
            #pragma unroll
            for (int i = 0; i < 2; i++)
                #pragma unroll
                for (int j = 0; j < 2; j++)
                    mma_tf32(acc[i][j], ah[i], bl[j]);
            #pragma unroll
            for (int i = 0; i < 2; i++)
                #pragma unroll
                for (int j = 0; j < 2; j++)
                    mma_tf32(acc[i][j], al[i], bh[j]);
        }
    }

    #pragma unroll
    for (int i = 0; i < 2; i++) {
        #pragma unroll
        for (int j = 0; j < 2; j++) {
            int rg = bm + wm * 32 + i * 16 + l2;
            int cg = bn + wn * 16 + j * 8 + 2 * l3;
            float bv0 = bias ? bias[cg] : 0.0f;
            float bv1 = bias ? bias[cg + 1] : 0.0f;
            float v0 = acc[i][j][0] + bv0, v1 = acc[i][j][1] + bv1;
            float v2 = acc[i][j][2] + bv0, v3 = acc[i][j][3] + bv1;
            if (act) { v0 = gelu_f(v0); v1 = gelu_f(v1); v2 = gelu_f(v2); v3 = gelu_f(v3); }
            *(float2*)(C + (size_t)rg * ldc + cg) = make_float2(v0, v1);
            *(float2*)(C + (size_t)(rg + 8) * ldc + cg) = make_float2(v2, v3);
        }
    }
}

// ---------------- 128x64 3xTF32 GEMM (encoder), BK=32, 3-stage, dyn smem -----
// 8 warps, warp grid 4(m) x 2(n), warp tile 32x32. non-trans B only.
#define SM128_FLOATS (3 * 128 * PADK + 3 * 32 * PADN)
#define SM128_BYTES  (SM128_FLOATS * 4)

__global__ __launch_bounds__(256, 2)
void gemm128(const float* __restrict__ A0, const float* __restrict__ A1, const float* __restrict__ A2,
             const float* __restrict__ W0, const float* __restrict__ W1, const float* __restrict__ W2,
             const float* __restrict__ bias0, const float* __restrict__ bias1, const float* __restrict__ bias2,
             float* __restrict__ C0, float* __restrict__ C1, float* __restrict__ C2,
             int M, int N, int K, int lda, int ldb, int ldc,
             int act,
             long long sA, long long sB, long long sC, int zPerSet) {
    int z = blockIdx.z;
    int set = z / zPerSet;
    int zz = z % zPerSet;

    const float* A  = (set == 0) ? A0 : (set == 1 ? A1 : A2);
    const float* Bm = (set == 0) ? W0 : (set == 1 ? W1 : W2);
    const float* bias = (set == 0) ? bias0 : (set == 1 ? bias1 : bias2);
    float* C = (set == 0) ? C0 : (set == 1 ? C1 : C2);
    A  += zz * sA;
    Bm += zz * sB;
    C  += zz * sC;

    extern __shared__ float sm[];
    float* Asm = sm;                      // [3][128][PADK]
    float* Bsm = sm + 3 * 128 * PADK;     // [3][32][PADN]

    int tid = threadIdx.x;
    int lane = tid & 31, wid = tid >> 5;
    int wm = wid >> 1, wn = wid & 1;      // 4m x 2n
    int l3 = lane & 3, l2 = lane >> 2;

    int bm = blockIdx.y * 128;
    int bn = blockIdx.x * 64;

    float acc[2][4][4] = {};
    int nk = K / 32;

    // A: 128 rows x 8 quads = 1024 quads, 4/thread. B: 32 rows x 16 quads = 512, 2/thread.
    #pragma unroll
    for (int p = 0; p < 2; p++) {
        int k0 = p * 32;
        float* As = Asm + p * 128 * PADK;
        float* Bs = Bsm + p * 32 * PADN;
        #pragma unroll
        for (int t = 0; t < 4; t++) {
            int q = tid + t * 256;
            int r = q >> 3, kq = (q & 7) * 4;
            cp16(&As[r * PADK + kq], A + (size_t)(bm + r) * lda + k0 + kq);
        }
        #pragma unroll
        for (int t = 0; t < 2; t++) {
            int q = tid + t * 256;
            int r = q >> 4, nc = (q & 15) * 4;
            cp16(&Bs[r * PADN + nc], Bm + (size_t)(k0 + r) * ldb + bn + nc);
        }
        CP_COMMIT();
    }

    for (int kt = 0; kt < nk; kt++) {
        CP_WAIT(1);
        __syncthreads();
        int st = kt % 3;
        if (kt + 2 < nk) {
            int ns = (kt + 2) % 3;
            int k0 = (kt + 2) * 32;
            float* As = Asm + ns * 128 * PADK;
            float* Bs = Bsm + ns * 32 * PADN;
            #pragma unroll
            for (int t = 0; t < 4; t++) {
                int q = tid + t * 256;
                int r = q >> 3, kq = (q & 7) * 4;
                cp16(&As[r * PADK + kq], A + (size_t)(bm + r) * lda + k0 + kq);
            }
            #pragma unroll
            for (int t = 0; t < 2; t++) {
                int q = tid + t * 256;
                int r = q >> 4, nc = (q & 15) * 4;
                cp16(&Bs[r * PADN + nc], Bm + (size_t)(k0 + r) * ldb + bn + nc);
            }
        }
        CP_COMMIT();

        const float* As = Asm + st * 128 * PADK;
        const float* Bs = Bsm + st * 32 * PADN;

        #pragma unroll
        for (int ks = 0; ks < 32; ks += 8) {
            unsigned ah[2][4], al[2][4], bh[4][2], bl[4][2];
            #pragma unroll
            for (int i = 0; i < 2; i++) {
                int m0 = wm * 32 + i * 16;
                split2(As[(m0 + l2) * PADK + ks + l3],         ah[i][0], al[i][0]);
                split2(As[(m0 + l2 + 8) * PADK + ks + l3],     ah[i][1], al[i][1]);
                split2(As[(m0 + l2) * PADK + ks + l3 + 4],     ah[i][2], al[i][2]);
                split2(As[(m0 + l2 + 8) * PADK + ks + l3 + 4], ah[i][3], al[i][3]);
            }
            #pragma unroll
            for (int j = 0; j < 4; j++) {
                int n0 = wn * 32 + j * 8;
                split2(Bs[(ks + l3) * PADN + n0 + l2],     bh[j][0], bl[j][0]);
                split2(Bs[(ks + l3 + 4) * PADN + n0 + l2], bh[j][1], bl[j][1]);
            }
            #pragma unroll
            for (int i = 0; i < 2; i++)
                #pragma unroll
                for (int j = 0; j < 4; j++)
                    mma_tf32(acc[i][j], ah[i], bh[j]);
            #pragma unroll
            for (int i = 0; i < 2; i++)
                #pragma unroll
                for (int j = 0; j < 4; j++)
                    mma_tf32(acc[i][j], ah[i], bl[j]);
            #pragma unroll
            for (int i = 0; i < 2; i++)
                #pragma unroll
                for (int j = 0; j < 4; j++)
                    mma_tf32(acc[i][j], al[i], bh[j]);
        }
    }

    #pragma unroll
    for (int i = 0; i < 2; i++) {
        #pragma unroll
        for (int j = 0; j < 4; j++) {
            int rg = bm + wm * 32 + i * 16 + l2;
            int cg = bn + wn * 32 + j * 8 + 2 * l3;
            float bv0 = bias ? bias[cg] : 0.0f;
            float bv1 = bias ? bias[cg + 1] : 0.0f;
            float v0 = acc[i][j][0] + bv0, v1 = acc[i][j][1] + bv1;
            float v2 = acc[i][j][2] + bv0, v3 = acc[i][j][3] + bv1;
            if (act) { v0 = gelu_f(v0); v1 = gelu_f(v1); v2 = gelu_f(v2); v3 = gelu_f(v3); }
            *(float2*)(C + (size_t)rg * ldc + cg) = make_float2(v0, v1);
            *(float2*)(C + (size_t)(rg + 8) * ldc + cg) = make_float2(v2, v3);
        }
    }
}

// ---------------- fused attention (R12 version) ------------------------------
#define APAD 132
#define QR 32
__global__ __launch_bounds__(256)
void fused_attn(const float* __restrict__ Q, const float* __restrict__ K,
                const float* __restrict__ V, float* __restrict__ O) {
    extern __shared__ float dyn[];
    float*  Qraw = dyn;
    float2* Qsp  = (float2*)(dyn + QR * APAD);
    float*  Kbuf = dyn + QR * APAD * 3;
    __shared__ float redM[QR][8];
    __shared__ float redS[QR][8];

    int bz = blockIdx.y;
    int bb = bz >> 2, h = bz & 3;
    int qbase = blockIdx.x * QR;

    int tid = threadIdx.x;
    int lane = tid & 31, wn = tid >> 5;
    int l3 = lane & 3, l2 = lane >> 2;

    const float* Qg = Q + ((size_t)bb * T + qbase) * D + h * DK;
    const float* Kg = K + ((size_t)bb * T) * D + h * DK;
    const float* Vg = V + ((size_t)bb * T) * D + h * DK;

    #pragma unroll
    for (int t = 0; t < 4; t++) {
        int idx = tid + t * 256;
        int r = idx >> 5, c = (idx & 31) * 4;
        cp16(&Qraw[r * APAD + c], Qg + (size_t)r * D + c);
    }
    CP_COMMIT();
    #pragma unroll
    for (int t = 0; t < 16; t++) {
        int idx = tid + t * 256;
        int r = idx >> 5, c = (idx & 31) * 4;
        cp16(&Kbuf[r * APAD + c], Kg + (size_t)r * D + c);
    }
    CP_COMMIT();
    CP_WAIT(0);
    __syncthreads();

    #pragma unroll
    for (int t = 0; t < 16; t++) {
        int idx = tid + t * 256;
        int r = idx >> 7, c = idx & 127;
        Qsp[r * APAD + c] = split2f(Qraw[r * APAD + c]);
    }
    __syncthreads();

    float acc[2][2][4] = {};
    #pragma unroll 4
    for (int ks = 0; ks < DK; ks += 8) {
        unsigned ah[2][4], al[2][4], bh[2][2], bl[2][2];
        #pragma unroll
        for (int i = 0; i < 2; i++) {
            int m0 = i * 16;
            float2 v0 = Qsp[(m0 + l2) * APAD + ks + l3];
            float2 v1 = Qsp[(m0 + l2 + 8) * APAD + ks + l3];
            float2 v2 = Qsp[(m0 + l2) * APAD + ks + l3 + 4];
            float2 v3 = Qsp[(m0 + l2 + 8) * APAD + ks + l3 + 4];
            ah[i][0] = __float_as_uint(v0.x); al[i][0] = __float_as_uint(v0.y);
            ah[i][1] = __float_as_uint(v1.x); al[i][1] = __float_as_uint(v1.y);
            ah[i][2] = __float_as_uint(v2.x); al[i][2] = __float_as_uint(v2.y);
            ah[i][3] = __float_as_uint(v3.x); al[i][3] = __float_as_uint(v3.y);
        }
        #pragma unroll
        for (int j = 0; j < 2; j++) {
            int n0 = wn * 16 + j * 8;
            split2(Kbuf[(n0 + l2) * APAD + ks + l3],     bh[j][0], bl[j][0]);
            split2(Kbuf[(n0 + l2) * APAD + ks + l3 + 4], bh[j][1], bl[j][1]);
        }
        #pragma unroll
        for (int i = 0; i < 2; i++)
            #pragma unroll
            for (int j = 0; j < 2; j++)
                mma_tf32(acc[i][j], ah[i], bh[j]);
        #pragma unroll
        for (int i = 0; i < 2; i++)
            #pragma unroll
            for (int j = 0; j < 2; j++)
                mma_tf32(acc[i][j], ah[i], bl[j]);
        #pragma unroll
        for (int i = 0; i < 2; i++)
            #pragma unroll
            for (int j = 0; j < 2; j++)
                mma_tf32(acc[i][j], al[i], bh[j]);
    }
    __syncthreads();

    #pragma unroll
    for (int t = 0; t < 16; t++) {
        int idx = tid + t * 256;
        int r = idx >> 5, c = (idx & 31) * 4;
        cp16(&Kbuf[r * APAD + c], Vg + (size_t)r * D + c);
    }
    CP_COMMIT();

    const float sc = 0.08838834764831845f;
    #pragma unroll
    for (int i = 0; i < 2; i++)
        #pragma unroll
        for (int j = 0; j < 2; j++)
            #pragma unroll
            for (int q = 0; q < 4; q++) acc[i][j][q] *= sc;

    #pragma unroll
    for (int i = 0; i < 2; i++)
        #pragma unroll
        for (int hf = 0; hf < 2; hf++) {
            int row = i * 16 + l2 + hf * 8;
            float m = fmaxf(fmaxf(acc[i][0][2 * hf], acc[i][0][2 * hf + 1]),
                            fmaxf(acc[i][1][2 * hf], acc[i][1][2 * hf + 1]));
            m = fmaxf(m, __shfl_xor_sync(0xffffffff, m, 1));
            m = fmaxf(m, __shfl_xor_sync(0xffffffff, m, 2));
            if (l3 == 0) redM[row][wn] = m;
        }
    __syncthreads();
    #pragma unroll
    for (int i = 0; i < 2; i++)
        #pragma unroll
        for (int hf = 0; hf < 2; hf++) {
            int row = i * 16 + l2 + hf * 8;
            float m = redM[row][0];
            #pragma unroll
            for (int w2 = 1; w2 < 8; w2++) m = fmaxf(m, redM[row][w2]);
            float s = 0.0f;
            #pragma unroll
            for (int j = 0; j < 2; j++) {
                acc[i][j][2 * hf]     = expf(acc[i][j][2 * hf] - m);
                acc[i][j][2 * hf + 1] = expf(acc[i][j][2 * hf + 1] - m);
                s += acc[i][j][2 * hf] + acc[i][j][2 * hf + 1];
            }
            s += __shfl_xor_sync(0xffffffff, s, 1);
            s += __shfl_xor_sync(0xffffffff, s, 2);
            if (l3 == 0) redS[row][wn] = s;
        }
    __syncthreads();
    #pragma unroll
    for (int i = 0; i < 2; i++)
        #pragma unroll
        for (int hf = 0; hf < 2; hf++) {
            int row = i * 16 + l2 + hf * 8;
            float ssum = redS[row][0];
            #pragma unroll
            for (int w2 = 1; w2 < 8; w2++) ssum += redS[row][w2];
            float inv = 1.0f / ssum;
            #pragma unroll
            for (int j = 0; j < 2; j++) {
                int col = wn * 16 + j * 8 + 2 * l3;
                Qsp[row * APAD + col]     = split2f(acc[i][j][2 * hf] * inv);
                Qsp[row * APAD + col + 1] = split2f(acc[i][j][2 * hf + 1] * inv);
            }
        }
    CP_WAIT(0);
    __syncthreads();

    float out[2][2][4] = {};
    #pragma unroll 4
    for (int ks = 0; ks < T; ks += 8) {
        unsigned ah[2][4], al[2][4], bh[2][2], bl[2][2];
        #pragma unroll
        for (int i = 0; i < 2; i++) {
            int m0 = i * 16;
            float2 v0 = Qsp[(m0 + l2) * APAD + ks + l3];
            float2 v1 = Qsp[(m0 + l2 + 8) * APAD + ks + l3];
            float2 v2 = Qsp[(m0 + l2) * APAD + ks + l3 + 4];
            float2 v3 = Qsp[(m0 + l2 + 8) * APAD + ks + l3 + 4];
            ah[i][0] = __float_as_uint(v0.x); al[i][0] = __float_as_uint(v0.y);
            ah[i][1] = __float_as_uint(v1.x); al[i][1] = __float_as_uint(v1.y);
            ah[i][2] = __float_as_uint(v2.x); al[i][2] = __float_as_uint(v2.y);
            ah[i][3] = __float_as_uint(v3.x); al[i][3] = __float_as_uint(v3.y);
        }
        #pragma unroll
        for (int j = 0; j < 2; j++) {
            int n0 = wn * 16 + j * 8;
            split2(Kbuf[(ks + l3) * APAD + n0 + l2],     bh[j][0], bl[j][0]);
            split2(Kbuf[(ks + l3 + 4) * APAD + n0 + l2], bh[j][1], bl[j][1]);
        }
        #pragma unroll
        for (int i = 0; i < 2; i++)
            #pragma unroll
            for (int j = 0; j < 2; j++)
                mma_tf32(out[i][j], ah[i], bh[j]);
        #pragma unroll
        for (int i = 0; i < 2; i++)
            #pragma unroll
            for (int j = 0; j < 2; j++)
                mma_tf32(out[i][j], ah[i], bl[j]);
        #pragma unroll
        for (int i = 0; i < 2; i++)
            #pragma unroll
            for (int j = 0; j < 2; j++)
                mma_tf32(out[i][j], al[i], bh[j]);
    }

    float* Og = O + ((size_t)bb * T + qbase) * D + h * DK;
    #pragma unroll
    for (int i = 0; i < 2; i++)
        #pragma unroll
        for (int j = 0; j < 2; j++) {
            int r = i * 16 + l2;
            int c = wn * 16 + j * 8 + 2 * l3;
            *(float2*)(Og + (size_t)r * D + c) = make_float2(out[i][j][0], out[i][j][1]);
            *(float2*)(Og + (size_t)(r + 8) * D + c) = make_float2(out[i][j][2], out[i][j][3]);
        }
}

// ---------------- warp helpers ----------------------------------------------
__device__ __forceinline__ float warp_sum(float v) {
    #pragma unroll
    for (int o = 16; o > 0; o >>= 1) v += __shfl_xor_sync(0xffffffff, v, o);
    return v;
}
__device__ __forceinline__ float warp_max(float v) {
    #pragma unroll
    for (int o = 16; o > 0; o >>= 1) v = fmaxf(v, __shfl_xor_sync(0xffffffff, v, o));
    return v;
}

// ---------------- LayerNorm kernels ------------------------------------------
__global__ void add_pos_ln_kernel(const float* __restrict__ qe, const float* __restrict__ ae,
                                  const float* __restrict__ pos,
                                  const float* __restrict__ w, const float* __restrict__ b,
                                  float* __restrict__ out) {
    int row = blockIdx.x, tid = threadIdx.x;
    int lane = tid & 31, wd = tid >> 5;
    __shared__ float p1[4], p2[4];

    const float* src = (row < 512) ? (qe + (size_t)row * D) : (ae + (size_t)(row - 512) * D);
    float4 xv = ((const float4*)src)[tid];
    float4 pv = ((const float4*)(pos + (size_t)(row % T) * D))[tid];
    float4 v = make_float4(xv.x + pv.x, xv.y + pv.y, xv.z + pv.z, xv.w + pv.w);

    float s = warp_sum(v.x + v.y + v.z + v.w);
    if (lane == 0) p1[wd] = s;
    __syncthreads();
    float mean = (p1[0] + p1[1] + p1[2] + p1[3]) * (1.0f / D);
    float4 d = make_float4(v.x - mean, v.y - mean, v.z - mean, v.w - mean);
    float q = warp_sum(d.x * d.x + d.y * d.y + d.z * d.z + d.w * d.w);
    if (lane == 0) p2[wd] = q;
    __syncthreads();
    float inv = rsqrtf((p2[0] + p2[1] + p2[2] + p2[3]) * (1.0f / D) + 1e-12f);

    float4 wv = ((const float4*)w)[tid];
    float4 bv = ((const float4*)b)[tid];
    ((float4*)(out + (size_t)row * D))[tid] =
        make_float4(wv.x * d.x * inv + bv.x, wv.y * d.y * inv + bv.y,
                    wv.z * d.z * inv + bv.z, wv.w * d.w * inv + bv.w);
}

// x += (sum of 4 partials) + gbias; persist; out = LN(x)*w+b
__global__ void residual_ln4_kernel(float* __restrict__ x, const float* __restrict__ yp,
                                    const float* __restrict__ gbias,
                                    float* __restrict__ out,
                                    const float* __restrict__ w, const float* __restrict__ b) {
    int row = blockIdx.x, tid = threadIdx.x;
    int lane = tid & 31, wd = tid >> 5;
    __shared__ float p1[4], p2[4];

    float4 v = ((const float4*)(x + (size_t)row * D))[tid];
    #pragma unroll
    for (int p = 0; p < 4; p++) {
        float4 yv = ((const float4*)(yp + (size_t)p * ND + (size_t)row * D))[tid];
        v.x += yv.x; v.y += yv.y; v.z += yv.z; v.w += yv.w;
    }
    float4 gb = ((const float4*)gbias)[tid];
    v.x += gb.x; v.y += gb.y; v.z += gb.z; v.w += gb.w;
    ((float4*)(x + (size_t)row * D))[tid] = v;

    float s = warp_sum(v.x + v.y + v.z + v.w);
    if (lane == 0) p1[wd] = s;
    __syncthreads();
    float mean = (p1[0] + p1[1] + p1[2] + p1[3]) * (1.0f / D);
    float4 d = make_float4(v.x - mean, v.y - mean, v.z - mean, v.w - mean);
    float q = warp_sum(d.x * d.x + d.y * d.y + d.z * d.z + d.w * d.w);
    if (lane == 0) p2[wd] = q;
    __syncthreads();
    float inv = rsqrtf((p2[0] + p2[1] + p2[2] + p2[3]) * (1.0f / D) + 1e-12f);

    float4 wv = ((const float4*)w)[tid];
    float4 bv = ((const float4*)b)[tid];
    ((float4*)(out + (size_t)row * D))[tid] =
        make_float4(wv.x * d.x * inv + bv.x, wv.y * d.y * inv + bv.y,
                    wv.z * d.z * inv + bv.z, wv.w * d.w * inv + bv.w);
}

// ---------------- sim head helpers ------------------------------------------
__global__ void edot_kernel(const float* __restrict__ X, const float* __restrict__ E,
                            float* __restrict__ out) {
    int row = blockIdx.x;
    int tid = threadIdx.x;
    __shared__ float red[NC * 256];
    float acc[NC] = {};
    for (int d = tid; d < D; d += 256) {
        float x = X[(size_t)row * D + d];
        #pragma unroll
        for (int c = 0; c < NC; c++) acc[c] += x * E[(size_t)c * D + d];
    }
    #pragma unroll
    for (int c = 0; c < NC; c++) red[c * 256 + tid] = acc[c];
    __syncthreads();
    for (int off = 128; off > 0; off >>= 1) {
        if (tid < off) {
            #pragma unroll
            for (int c = 0; c < NC; c++) red[c * 256 + tid] += red[c * 256 + tid + off];
        }
        __syncthreads();
    }
    if (tid < NC) out[(size_t)row * NC + tid] = red[tid * 256];
}

__global__ void gram_kernel(const float* __restrict__ E, float* __restrict__ G) {
    int i = threadIdx.x;
    if (i < NC * NC) {
        int c = i / NC, c2 = i % NC;
        float s = 0.0f;
        for (int d = 0; d < D; d++) s += E[(size_t)c * D + d] * E[(size_t)c2 * D + d];
        G[i] = s;
    }
}

__global__ void sim_attn_kernel(const float* __restrict__ QK, const float* __restrict__ QK2,
                                const float* __restrict__ qa,
                                const float* __restrict__ aq, const float* __restrict__ Eq,
                                const float* __restrict__ Ek, const float* __restrict__ G,
                                float* __restrict__ P, float* __restrict__ Wout) {
    int t = blockIdx.x, b = blockIdx.y;
    int s = threadIdx.x;
    int lane = s & 31, wd = s >> 5;
    __shared__ float g[NC * NC];
    __shared__ float part[4];
    __shared__ float pv[T];
    if (s < NC * NC) g[s] = G[s];
    __syncthreads();

    float f1[NC], f2[NC];
    const float* r1 = qa + (((size_t)b * T + t) * T + s) * NC;
    const float* r2 = aq + (((size_t)b * T + s) * T + t) * NC;
    #pragma unroll
    for (int c = 0; c < NC; c++) { f1[c] = r1[c]; f2[c] = r2[c]; }

    size_t qkidx = ((size_t)b * T + t) * T + s;
    float sc = QK[qkidx] + QK2[qkidx];
    const float* eq = Eq + ((size_t)b * T + t) * NC;
    const float* ek = Ek + ((size_t)b * T + s) * NC;
    #pragma unroll
    for (int c = 0; c < NC; c++) sc += f1[c] * ek[c] + f2[c] * eq[c];
    #pragma unroll
    for (int c = 0; c < NC; c++)
        #pragma unroll
        for (int c2 = 0; c2 < NC; c2++)
            sc += f1[c] * g[c * NC + c2] * f2[c2];

    float m = warp_max(sc);
    if (lane == 0) part[wd] = m;
    __syncthreads();
    float m1 = fmaxf(fmaxf(part[0], part[1]), fmaxf(part[2], part[3]));
    float e1 = expf(sc - m1);
    float ssum = warp_sum(e1);
    if (lane == 0) part[wd] = ssum;
    __syncthreads();
    float p = e1 / (part[0] + part[1] + part[2] + part[3]);

    float l = 1000.0f * p;
    m = warp_max(l);
    __syncthreads();
    if (lane == 0) part[wd] = m;
    __syncthreads();
    float m2 = fmaxf(fmaxf(part[0], part[1]), fmaxf(part[2], part[3]));
    float e2 = expf(l - m2);
    ssum = warp_sum(e2);
    __syncthreads();
    if (lane == 0) part[wd] = ssum;
    __syncthreads();
    float p2 = e2 / (part[0] + part[1] + part[2] + part[3]);
    p2 = fminf(fmaxf(p2, 0.0f), 1.0f);

    P[((size_t)b * T + t) * T + s] = p2;
    pv[s] = p2;
    __syncthreads();

    #pragma unroll
    for (int c = 0; c < NC; c++) {
        float v = warp_sum(pv[s] * f2[c]);
        __syncthreads();
        if (lane == 0) part[wd] = v;
        __syncthreads();
        if (s == 0) Wout[((size_t)b * T + t) * NC + c] = part[0] + part[1] + part[2] + part[3];
    }
}

__global__ void final_kernel(const float* __restrict__ pk, const float* __restrict__ pk2,
                             const float* __restrict__ Wm,
                             const float* __restrict__ E, const float* __restrict__ clsw,
                             const float* __restrict__ clsb, float* __restrict__ out) {
    int b = blockIdx.x;
    int d = threadIdx.x;
    __shared__ float wm[NC];
    __shared__ float red[512];

    if (d < NC) {
        float s = 0.0f;
        for (int t = 0; t < T; t++) s += Wm[((size_t)b * T + t) * NC + d];
        wm[d] = s * (1.0f / T);
    }
    __syncthreads();

    float s = 0.0f;
    for (int t = 0; t < T; t++)
        s += pk[((size_t)b * T + t) * D + d] + pk2[((size_t)b * T + t) * D + d];
    s *= (1.0f / T);
    #pragma unroll
    for (int c = 0; c < NC; c++) s += wm[c] * E[(size_t)c * D + d];

    for (int j = 0; j < 3; j++) {
        red[d] = s * clsw[(size_t)d * 3 + j];
        __syncthreads();
        for (int off = 256; off > 0; off >>= 1) { if (d < off) red[d] += red[d + off]; __syncthreads(); }
        if (d == 0) out[b * 3 + j] = red[0] + clsb[j];
        __syncthreads();
    }
}

// ---------------- host orchestration ----------------------------------------
static inline void g_launch(int transB,
                            const float* A0, const float* A1, const float* A2,
                            const float* W0, const float* W1, const float* W2,
                            const float* b0, const float* b1, const float* b2,
                            float* C0, float* C1, float* C2,
                            int M, int N, int K, int lda, int ldb, int ldc,
                            int act, int nH,
                            long long sA, long long hA, long long sB, long long hB,
                            long long sC, long long hC, int zPerSet, int nz) {
    dim3 grid(N / 64, M / 64, nz);
    if (transB)
        gemm_tf32<1><<<grid, 256>>>(A0, A1, A2, W0, W1, W2, b0, b1, b2, C0, C1, C2,
                                    M, N, K, lda, ldb, ldc, act, nH,
                                    sA, hA, sB, hB, sC, hC, zPerSet);
    else
        gemm_tf32<0><<<grid, 256>>>(A0, A1, A2, W0, W1, W2, b0, b1, b2, C0, C1, C2,
                                    M, N, K, lda, ldb, ldc, act, nH,
                                    sA, hA, sB, hB, sC, hC, zPerSet);
}

extern "C" void kernel_launch(void* const* d_in, const int* in_sizes, int n_in,
                              void* d_out, int out_size) {
    const float* q_emb   = (const float*)d_in[0];
    const float* a_emb   = (const float*)d_in[1];
    const float* qa_rel  = (const float*)d_in[2];
    const float* aq_rel  = (const float*)d_in[3];
    const float* conceptE= (const float*)d_in[4];
    const float* pos_emb = (const float*)d_in[5];
    const float* pe_w    = (const float*)d_in[6];
    const float* pe_b    = (const float*)d_in[7];
    const float* Wq      = (const float*)d_in[8];
    const float* bq      = (const float*)d_in[9];
    const float* Wk      = (const float*)d_in[10];
    const float* bk      = (const float*)d_in[11];
    const float* Wv      = (const float*)d_in[12];
    const float* bv      = (const float*)d_in[13];
    const float* Wo      = (const float*)d_in[14];
    const float* bo      = (const float*)d_in[15];
    const float* ff1w    = (const float*)d_in[16];
    const float* ff1b    = (const float*)d_in[17];
    const float* ff2w    = (const float*)d_in[18];
    const float* ff2b    = (const float*)d_in[19];
    const float* lninw   = (const float*)d_in[20];
    const float* lninb   = (const float*)d_in[21];
    const float* lnoutw  = (const float*)d_in[22];
    const float* lnoutb  = (const float*)d_in[23];
    const float* simWq   = (const float*)d_in[24];
    const float* simbq   = (const float*)d_in[25];
    const float* simWk   = (const float*)d_in[26];
    const float* simbk   = (const float*)d_in[27];
    const float* clsw    = (const float*)d_in[28];
    const float* clsb    = (const float*)d_in[29];
    float* out = (float*)d_out;

    float* base = nullptr;
    cudaGetSymbolAddress((void**)&base, g_scratch);

    float* X   = base + OFF_X;
    float* Qb  = base + OFF_Q;
    float* Kb  = base + OFF_K;
    float* Vb  = base + OFF_V;
    float* T0  = base + OFF_T0;
    float* TP  = base + OFF_TP;     // 4 contiguous partials
    float* Hb  = base + OFF_H;
    float* FFN = base + OFF_FFN;
    float* QKb = base + OFF_QK;
    float* QK2b= base + OFF_QK2;
    float* Pb  = base + OFF_P;
    float* EQb = base + OFF_EQ;
    float* EKb = base + OFF_EK;
    float* Gb  = base + OFF_G;
    float* Wb  = base + OFF_W;
    float* PKb = base + OFF_PK;
    float* PK2b= base + OFF_PK2;

    static const int ATTN_SMEM = (QR * APAD * 3 + 128 * APAD) * 4;
    cudaFuncSetAttribute(fused_attn, cudaFuncAttributeMaxDynamicSharedMemorySize, ATTN_SMEM);
    cudaFuncSetAttribute(gemm128, cudaFuncAttributeMaxDynamicSharedMemorySize, SM128_BYTES);

    add_pos_ln_kernel<<<M2, 128>>>(q_emb, a_emb, pos_emb, pe_w, pe_b, X);

    for (int i = 0; i < NL; i++) {
        const float* wq = Wq + (size_t)i * D * D;
        const float* wk = Wk + (size_t)i * D * D;
        const float* wv = Wv + (size_t)i * D * D;
        const float* wo = Wo + (size_t)i * D * D;

        // fused QKV: grid (8, 8, 3) = 192 CTAs, 128x64 tiles
        gemm128<<<dim3(8, 8, 3), 256, SM128_BYTES>>>(
            X, X, X, wq, wk, wv,
            bq + (size_t)i * D, bk + (size_t)i * D, bv + (size_t)i * D,
            Qb, Kb, Vb, M2, D, D, D, D, D, 0, 0, 0, 0, 1);

        fused_attn<<<dim3(4, 32), 256, ATTN_SMEM>>>(Qb, Kb, Vb, T0);

        // output projection split-K=4 (grid 8x8x4 = 256), bias in combine
        gemm128<<<dim3(8, 8, 4), 256, SM128_BYTES>>>(
            T0, 0, 0, wo, 0, 0, 0, 0, 0, TP, 0, 0,
            M2, D, 128, D, D, D, 0,
            128, (long long)128 * D, ND, 4);

        residual_ln4_kernel<<<M2, 128>>>(X, TP, bo + (size_t)i * D, Hb,
                                         lninw + (size_t)i * D, lninb + (size_t)i * D);

        // ff1 (grid 32x8 = 256, gelu)
        gemm128<<<dim3(32, 8, 1), 256, SM128_BYTES>>>(
            Hb, 0, 0, ff1w + (size_t)i * D * DFF, 0, 0,
            ff1b + (size_t)i * DFF, 0, 0, FFN, 0, 0,
            M2, DFF, D, D, DFF, DFF, 1, 0, 0, 0, 1);

        // ff2 split-K=4 (grid 8x8x4 = 256), bias in combine
        gemm128<<<dim3(8, 8, 4), 256, SM128_BYTES>>>(
            FFN, 0, 0, ff2w + (size_t)i * DFF * D, 0, 0, 0, 0, 0, TP, 0, 0,
            M2, D, 512, DFF, D, D, 0,
            512, (long long)512 * D, ND, 4);

        residual_ln4_kernel<<<M2, 128>>>(X, TP, ff2b + (size_t)i * D, X,
                                         lnoutw + (size_t)i * D, lnoutb + (size_t)i * D);
    }

    // --- sim head (64x64 path) ---
    g_launch(0, X, X + (size_t)(M2 / 2) * D, 0, simWq, simWk, 0, simbq, simbk, 0, Qb, Kb, 0,
             M2 / 2, D, D, D, D, D, 0, 1, 0, 0, 0, 0, 0, 0, 1, 2);

    edot_kernel<<<M2 / 2, 256>>>(Qb, conceptE, EQb);
    edot_kernel<<<M2 / 2, 256>>>(Kb, conceptE, EKb);
    gram_kernel<<<1, 32>>>(conceptE, Gb);

    g_launch(1, Qb, Qb + 256, 0, Kb, Kb + 256, 0, 0, 0, 0, QKb, QK2b, 0,
             T, T, 256, D, D, T, 0, 1,
             (long long)T * D, 0, (long long)T * D, 0, (long long)T * T, 0, 4, 8);

    sim_attn_kernel<<<dim3(T, Bb), 128>>>(QKb, QK2b, qa_rel, aq_rel, EQb, EKb, Gb, Pb, Wb);

    g_launch(0, Pb, Pb + 64, 0, Kb, Kb + (size_t)64 * D, 0, 0, 0, 0, PKb, PK2b, 0,
             T, D, 64, T, D, D, 0, 1,
             (long long)T * T, 0, (long long)T * D, 0, (long long)T * D, 0, 4, 8);

    final_kernel<<<Bb, 512>>>(PKb, PK2b, Wb, conceptE, clsw, clsb, out);
}

// round 15
// speedup vs baseline: 1.4972x; 1.0421x over previous
#include <cuda_runtime.h>
#include <cuda_bf16.h>
#include <math.h>

// Problem constants
#define Bb   4
#define T    128
#define D    512
#define Hh   4
#define DK   128
#define NL   4
#define DFF  2048
#define NC   5

#define M2   1024
#define ND   (M2*D)

// ---------------- scratch ----------------------------------------------------
#define OFF_X   0
#define OFF_Q   (1*ND)
#define OFF_K   (2*ND)
#define OFF_V   (3*ND)
#define OFF_T0  (4*ND)
#define OFF_TP  (5*ND)              // 4 contiguous split-K partials: 5..9 ND
#define OFF_H   (9*ND)
#define OFF_FFN (10*ND)             // M2*DFF = 4*ND -> ..14 ND
#define OFF_QK  (14*ND)
#define OFF_P   (OFF_QK + 65536)
#define OFF_EQ  (OFF_P + 65536)
#define OFF_EK  (OFF_EQ + 2560)
#define OFF_G   (OFF_EK + 2560)
#define OFF_W   (OFF_G + 32)
#define OFF_PK  (OFF_W + 2560)
#define OFF_QK2 (OFF_PK + 262144)
#define OFF_PK2 (OFF_QK2 + 65536)
#define SCRATCH_TOTAL (OFF_PK2 + 262144)

__device__ float g_scratch[SCRATCH_TOTAL];

__device__ __forceinline__ float gelu_f(float x) {
    return 0.5f * x * (1.0f + erff(x * 0.7071067811865475f));
}

// ---------------- tf32 / mma / cp.async helpers ------------------------------
__device__ __forceinline__ unsigned f2tf32(float x) {
    unsigned r;
    asm("cvt.rna.tf32.f32 %0, %1;" : "=r"(r) : "f"(x));
    return r;
}
__device__ __forceinline__ void split2(float x, unsigned& hi, unsigned& lo) {
    hi = f2tf32(x);
    lo = f2tf32(x - __uint_as_float(hi));
}
__device__ __forceinline__ float2 split2f(float x) {
    unsigned h, l;
    split2(x, h, l);
    return make_float2(__uint_as_float(h), __uint_as_float(l));
}
__device__ __forceinline__ void mma_tf32(float* c, const unsigned* a, const unsigned* b) {
    asm volatile(
        "mma.sync.aligned.m16n8k8.row.col.f32.tf32.tf32.f32 "
        "{%0,%1,%2,%3},{%4,%5,%6,%7},{%8,%9},{%0,%1,%2,%3};"
        : "+f"(c[0]), "+f"(c[1]), "+f"(c[2]), "+f"(c[3])
        : "r"(a[0]), "r"(a[1]), "r"(a[2]), "r"(a[3]), "r"(b[0]), "r"(b[1]));
}
__device__ __forceinline__ void cp16(void* s, const void* g) {
    unsigned sa = (unsigned)__cvta_generic_to_shared(s);
    asm volatile("cp.async.cg.shared.global [%0], [%1], 16;\n" :: "r"(sa), "l"(g) : "memory");
}
#define CP_COMMIT() asm volatile("cp.async.commit_group;\n" ::: "memory")
#define CP_WAIT(n)  asm volatile("cp.async.wait_group %0;\n" :: "n"(n) : "memory")

// ---------------- 64x64 3xTF32 GEMM (sim head), BK=32, 3-stage ---------------
#define PADK 36
#define PADN 72

template<int TRANSB>
__global__ __launch_bounds__(256, 2)
void gemm_tf32(const float* __restrict__ A0, const float* __restrict__ A1, const float* __restrict__ A2,
               const float* __restrict__ W0, const float* __restrict__ W1, const float* __restrict__ W2,
               const float* __restrict__ bias0, const float* __restrict__ bias1, const float* __restrict__ bias2,
               float* __restrict__ C0, float* __restrict__ C1, float* __restrict__ C2,
               int M, int N, int K, int lda, int ldb, int ldc,
               int act, int nH,
               long long sA, long long hA, long long sB, long long hB,
               long long sC, long long hC, int zPerSet) {
    int z = blockIdx.z;
    int set = z / zPerSet;
    int zz = z % zPerSet;
    int bb = zz / nH, hh = zz % nH;

    const float* A  = (set == 0) ? A0 : (set == 1 ? A1 : A2);
    const float* Bm = (set == 0) ? W0 : (set == 1 ? W1 : W2);
    const float* bias = (set == 0) ? bias0 : (set == 1 ? bias1 : bias2);
    float* C = (set == 0) ? C0 : (set == 1 ? C1 : C2);
    A  += bb * sA + hh * hA;
    Bm += bb * sB + hh * hB;
    C  += bb * sC + hh * hC;

    __shared__ float As[3][64][PADK];
    constexpr int BR = TRANSB ? 64 : 32;
    constexpr int BC = TRANSB ? PADK : PADN;
    __shared__ float Bs[3][BR][BC];

    int tid = threadIdx.x;
    int lane = tid & 31, wid = tid >> 5;
    int wm = wid & 1, wn = wid >> 1;
    int l3 = lane & 3, l2 = lane >> 2;

    int bm = blockIdx.y * 64;
    int bn = blockIdx.x * 64;

    int ar = tid >> 2, ak = (tid & 3) * 4;
    int nbr = tid >> 4, nbc = (tid & 15) * 4;

    float acc[2][2][4] = {};

    int nk = K / 32;

    #pragma unroll
    for (int p = 0; p < 2; p++) {
        int k0 = p * 32;
        cp16(&As[p][ar][ak],      A + (size_t)(bm + ar) * lda + k0 + ak);
        cp16(&As[p][ar][ak + 16], A + (size_t)(bm + ar) * lda + k0 + 16 + ak);
        if (TRANSB) {
            cp16(&Bs[p][ar][ak],      Bm + (size_t)(bn + ar) * ldb + k0 + ak);
            cp16(&Bs[p][ar][ak + 16], Bm + (size_t)(bn + ar) * ldb + k0 + 16 + ak);
        } else {
            cp16(&Bs[p][nbr][nbc],      Bm + (size_t)(k0 + nbr) * ldb + bn + nbc);
            cp16(&Bs[p][nbr + 16][nbc], Bm + (size_t)(k0 + nbr + 16) * ldb + bn + nbc);
        }
        CP_COMMIT();
    }

    for (int kt = 0; kt < nk; kt++) {
        CP_WAIT(1);
        __syncthreads();
        int st = kt % 3;
        if (kt + 2 < nk) {
            int ns = (kt + 2) % 3;
            int k0 = (kt + 2) * 32;
            cp16(&As[ns][ar][ak],      A + (size_t)(bm + ar) * lda + k0 + ak);
            cp16(&As[ns][ar][ak + 16], A + (size_t)(bm + ar) * lda + k0 + 16 + ak);
            if (TRANSB) {
                cp16(&Bs[ns][ar][ak],      Bm + (size_t)(bn + ar) * ldb + k0 + ak);
                cp16(&Bs[ns][ar][ak + 16], Bm + (size_t)(bn + ar) * ldb + k0 + 16 + ak);
            } else {
                cp16(&Bs[ns][nbr][nbc],      Bm + (size_t)(k0 + nbr) * ldb + bn + nbc);
                cp16(&Bs[ns][nbr + 16][nbc], Bm + (size_t)(k0 + nbr + 16) * ldb + bn + nbc);
            }
        }
        CP_COMMIT();

        #pragma unroll
        for (int ks = 0; ks < 32; ks += 8) {
            unsigned ah[2][4], al[2][4], bh[2][2], bl[2][2];
            #pragma unroll
            for (int i = 0; i < 2; i++) {
                int m0 = wm * 32 + i * 16;
                split2(As[st][m0 + l2][ks + l3],         ah[i][0], al[i][0]);
                split2(As[st][m0 + l2 + 8][ks + l3],     ah[i][1], al[i][1]);
                split2(As[st][m0 + l2][ks + l3 + 4],     ah[i][2], al[i][2]);
                split2(As[st][m0 + l2 + 8][ks + l3 + 4], ah[i][3], al[i][3]);
            }
            #pragma unroll
            for (int j = 0; j < 2; j++) {
                int n0 = wn * 16 + j * 8;
                if (TRANSB) {
                    split2(Bs[st][n0 + l2][ks + l3],     bh[j][0], bl[j][0]);
                    split2(Bs[st][n0 + l2][ks + l3 + 4], bh[j][1], bl[j][1]);
                } else {
                    split2(Bs[st][ks + l3][n0 + l2],     bh[j][0], bl[j][0]);
                    split2(Bs[st][ks + l3 + 4][n0 + l2], bh[j][1], bl[j][1]);
                }
            }
            #pragma unroll
            for (int i = 0; i < 2; i++)
                #pragma unroll
                for (int j = 0; j < 2; j++)
                    mma_tf32(acc[i][j], ah[i], bh[j]);
            #pragma unroll
            for (int i = 0; i < 2; i++)
                #pragma unroll
                for (int j = 0; j < 2; j++)
                    mma_tf32(acc[i][j], ah[i], bl[j]);
            #pragma unroll
            for (int i = 0; i < 2; i++)
                #pragma unroll
                for (int j = 0; j < 2; j++)
                    mma_tf32(acc[i][j], al[i], bh[j]);
        }
    }

    #pragma unroll
    for (int i = 0; i < 2; i++) {
        #pragma unroll
        for (int j = 0; j < 2; j++) {
            int rg = bm + wm * 32 + i * 16 + l2;
            int cg = bn + wn * 16 + j * 8 + 2 * l3;
            float bv0 = bias ? bias[cg] : 0.0f;
            float bv1 = bias ? bias[cg + 1] : 0.0f;
            float v0 = acc[i][j][0] + bv0, v1 = acc[i][j][1] + bv1;
            float v2 = acc[i][j][2] + bv0, v3 = acc[i][j][3] + bv1;
            if (act) { v0 = gelu_f(v0); v1 = gelu_f(v1); v2 = gelu_f(v2); v3 = gelu_f(v3); }
            *(float2*)(C + (size_t)rg * ldc + cg) = make_float2(v0, v1);
            *(float2*)(C + (size_t)(rg + 8) * ldc + cg) = make_float2(v2, v3);
        }
    }
}

// ---------------- 128x64 3xTF32 GEMM (encoder), BK=64, 2-stage, dyn smem -----
// 8 warps, warp grid 4(m) x 2(n), warp tile 32x32. non-trans B only.
#define PK128 68
#define SM128_FLOATS (2 * 128 * PK128 + 2 * 64 * PADN)
#define SM128_BYTES  (SM128_FLOATS * 4)

__global__ __launch_bounds__(256, 2)
void gemm128(const float* __restrict__ A0, const float* __restrict__ A1, const float* __restrict__ A2,
             const float* __restrict__ W0, const float* __restrict__ W1, const float* __restrict__ W2,
             const float* __restrict__ bias0, const float* __restrict__ bias1, const float* __restrict__ bias2,
             float* __restrict__ C0, float* __restrict__ C1, float* __restrict__ C2,
             int M, int N, int K, int lda, int ldb, int ldc,
             int act,
             long long sA, long long sB, long long sC, int zPerSet) {
    int z = blockIdx.z;
    int set = z / zPerSet;
    int zz = z % zPerSet;

    const float* A  = (set == 0) ? A0 : (set == 1 ? A1 : A2);
    const float* Bm = (set == 0) ? W0 : (set == 1 ? W1 : W2);
    const float* bias = (set == 0) ? bias0 : (set == 1 ? bias1 : bias2);
    float* C = (set == 0) ? C0 : (set == 1 ? C1 : C2);
    A  += zz * sA;
    Bm += zz * sB;
    C  += zz * sC;

    extern __shared__ float sm[];
    float* Asm = sm;                      // [2][128][PK128]
    float* Bsm = sm + 2 * 128 * PK128;    // [2][64][PADN]

    int tid = threadIdx.x;
    int lane = tid & 31, wid = tid >> 5;
    int wm = wid >> 1, wn = wid & 1;      // 4m x 2n
    int l3 = lane & 3, l2 = lane >> 2;

    int bm = blockIdx.y * 128;
    int bn = blockIdx.x * 64;

    float acc[2][4][4] = {};
    int nk = K / 64;

    // loaders: A 128 rows x 16 quads = 2048 quads, 8/thread. B: 64 rows x 16 quads = 1024, 4/thread.
    {
        float* As = Asm;
        float* Bs = Bsm;
        #pragma unroll
        for (int t = 0; t < 8; t++) {
            int q = tid + t * 256;
            int r = q >> 4, kq = (q & 15) * 4;
            cp16(&As[r * PK128 + kq], A + (size_t)(bm + r) * lda + kq);
        }
        #pragma unroll
        for (int t = 0; t < 4; t++) {
            int q = tid + t * 256;
            int r = q >> 4, nc = (q & 15) * 4;
            cp16(&Bs[r * PADN + nc], Bm + (size_t)r * ldb + bn + nc);
        }
        CP_COMMIT();
    }

    for (int kt = 0; kt < nk; kt++) {
        if (kt + 1 < nk) {
            int ns = (kt + 1) & 1;
            int k0 = (kt + 1) * 64;
            float* As = Asm + ns * 128 * PK128;
            float* Bs = Bsm + ns * 64 * PADN;
            #pragma unroll
            for (int t = 0; t < 8; t++) {
                int q = tid + t * 256;
                int r = q >> 4, kq = (q & 15) * 4;
                cp16(&As[r * PK128 + kq], A + (size_t)(bm + r) * lda + k0 + kq);
            }
            #pragma unroll
            for (int t = 0; t < 4; t++) {
                int q = tid + t * 256;
                int r = q >> 4, nc = (q & 15) * 4;
                cp16(&Bs[r * PADN + nc], Bm + (size_t)(k0 + r) * ldb + bn + nc);
            }
            CP_COMMIT();
            CP_WAIT(1);
        } else {
            CP_WAIT(0);
        }
        __syncthreads();

        const float* As = Asm + (kt & 1) * 128 * PK128;
        const float* Bs = Bsm + (kt & 1) * 64 * PADN;

        #pragma unroll
        for (int ks = 0; ks < 64; ks += 8) {
            unsigned ah[2][4], al[2][4], bh[4][2], bl[4][2];
            #pragma unroll
            for (int i = 0; i < 2; i++) {
                int m0 = wm * 32 + i * 16;
                split2(As[(m0 + l2) * PK128 + ks + l3],         ah[i][0], al[i][0]);
                split2(As[(m0 + l2 + 8) * PK128 + ks + l3],     ah[i][1], al[i][1]);
                split2(As[(m0 + l2) * PK128 + ks + l3 + 4],     ah[i][2], al[i][2]);
                split2(As[(m0 + l2 + 8) * PK128 + ks + l3 + 4], ah[i][3], al[i][3]);
            }
            #pragma unroll
            for (int j = 0; j < 4; j++) {
                int n0 = wn * 32 + j * 8;
                split2(Bs[(ks + l3) * PADN + n0 + l2],     bh[j][0], bl[j][0]);
                split2(Bs[(ks + l3 + 4) * PADN + n0 + l2], bh[j][1], bl[j][1]);
            }
            #pragma unroll
            for (int i = 0; i < 2; i++)
                #pragma unroll
                for (int j = 0; j < 4; j++)
                    mma_tf32(acc[i][j], ah[i], bh[j]);
            #pragma unroll
            for (int i = 0; i < 2; i++)
                #pragma unroll
                for (int j = 0; j < 4; j++)
                    mma_tf32(acc[i][j], ah[i], bl[j]);
            #pragma unroll
            for (int i = 0; i < 2; i++)
                #pragma unroll
                for (int j = 0; j < 4; j++)
                    mma_tf32(acc[i][j], al[i], bh[j]);
        }
        __syncthreads();
    }

    #pragma unroll
    for (int i = 0; i < 2; i++) {
        #pragma unroll
        for (int j = 0; j < 4; j++) {
            int rg = bm + wm * 32 + i * 16 + l2;
            int cg = bn + wn * 32 + j * 8 + 2 * l3;
            float bv0 = bias ? bias[cg] : 0.0f;
            float bv1 = bias ? bias[cg + 1] : 0.0f;
            float v0 = acc[i][j][0] + bv0, v1 = acc[i][j][1] + bv1;
            float v2 = acc[i][j][2] + bv0, v3 = acc[i][j][3] + bv1;
            if (act) { v0 = gelu_f(v0); v1 = gelu_f(v1); v2 = gelu_f(v2); v3 = gelu_f(v3); }
            *(float2*)(C + (size_t)rg * ldc + cg) = make_float2(v0, v1);
            *(float2*)(C + (size_t)(rg + 8) * ldc + cg) = make_float2(v2, v3);
        }
    }
}

// ---------------- fused attention: Qsp-only smem (2 CTAs/SM) -----------------
#define APAD 132
#define QR 32
__global__ __launch_bounds__(256)
void fused_attn(const float* __restrict__ Q, const float* __restrict__ K,
                const float* __restrict__ V, float* __restrict__ O) {
    extern __shared__ float dyn[];
    float2* Qsp  = (float2*)dyn;                  // [QR][APAD] float2
    float*  Kbuf = dyn + QR * APAD * 2;           // [128][APAD] float
    __shared__ float redM[QR][8];
    __shared__ float redS[QR][8];

    int bz = blockIdx.y;
    int bb = bz >> 2, h = bz & 3;
    int qbase = blockIdx.x * QR;

    int tid = threadIdx.x;
    int lane = tid & 31, wn = tid >> 5;
    int l3 = lane & 3, l2 = lane >> 2;

    const float* Qg = Q + ((size_t)bb * T + qbase) * D + h * DK;
    const float* Kg = K + ((size_t)bb * T) * D + h * DK;
    const float* Vg = V + ((size_t)bb * T) * D + h * DK;

    // K via cp.async; Q via registers (small)
    #pragma unroll
    for (int t = 0; t < 16; t++) {
        int idx = tid + t * 256;
        int r = idx >> 5, c = (idx & 31) * 4;
        cp16(&Kbuf[r * APAD + c], Kg + (size_t)r * D + c);
    }
    CP_COMMIT();

    // Q: 32x128 = 4096 elems = 1024 float4; 4 float4/thread -> split to Qsp
    {
        #pragma unroll
        for (int t = 0; t < 4; t++) {
            int q = tid + t * 256;
            int r = q >> 5, c = (q & 31) * 4;
            float4 v = *(const float4*)(Qg + (size_t)r * D + c);
            Qsp[r * APAD + c]     = split2f(v.x);
            Qsp[r * APAD + c + 1] = split2f(v.y);
            Qsp[r * APAD + c + 2] = split2f(v.z);
            Qsp[r * APAD + c + 3] = split2f(v.w);
        }
    }
    CP_WAIT(0);
    __syncthreads();

    float acc[2][2][4] = {};
    #pragma unroll 4
    for (int ks = 0; ks < DK; ks += 8) {
        unsigned ah[2][4], al[2][4], bh[2][2], bl[2][2];
        #pragma unroll
        for (int i = 0; i < 2; i++) {
            int m0 = i * 16;
            float2 v0 = Qsp[(m0 + l2) * APAD + ks + l3];
            float2 v1 = Qsp[(m0 + l2 + 8) * APAD + ks + l3];
            float2 v2 = Qsp[(m0 + l2) * APAD + ks + l3 + 4];
            float2 v3 = Qsp[(m0 + l2 + 8) * APAD + ks + l3 + 4];
            ah[i][0] = __float_as_uint(v0.x); al[i][0] = __float_as_uint(v0.y);
            ah[i][1] = __float_as_uint(v1.x); al[i][1] = __float_as_uint(v1.y);
            ah[i][2] = __float_as_uint(v2.x); al[i][2] = __float_as_uint(v2.y);
            ah[i][3] = __float_as_uint(v3.x); al[i][3] = __float_as_uint(v3.y);
        }
        #pragma unroll
        for (int j = 0; j < 2; j++) {
            int n0 = wn * 16 + j * 8;
            split2(Kbuf[(n0 + l2) * APAD + ks + l3],     bh[j][0], bl[j][0]);
            split2(Kbuf[(n0 + l2) * APAD + ks + l3 + 4], bh[j][1], bl[j][1]);
        }
        #pragma unroll
        for (int i = 0; i < 2; i++)
            #pragma unroll
            for (int j = 0; j < 2; j++)
                mma_tf32(acc[i][j], ah[i], bh[j]);
        #pragma unroll
        for (int i = 0; i < 2; i++)
            #pragma unroll
            for (int j = 0; j < 2; j++)
                mma_tf32(acc[i][j], ah[i], bl[j]);
        #pragma unroll
        for (int i = 0; i < 2; i++)
            #pragma unroll
            for (int j = 0; j < 2; j++)
                mma_tf32(acc[i][j], al[i], bh[j]);
    }
    __syncthreads();

    #pragma unroll
    for (int t = 0; t < 16; t++) {
        int idx = tid + t * 256;
        int r = idx >> 5, c = (idx & 31) * 4;
        cp16(&Kbuf[r * APAD + c], Vg + (size_t)r * D + c);
    }
    CP_COMMIT();

    const float sc = 0.08838834764831845f;
    #pragma unroll
    for (int i = 0; i < 2; i++)
        #pragma unroll
        for (int j = 0; j < 2; j++)
            #pragma unroll
            for (int q = 0; q < 4; q++) acc[i][j][q] *= sc;

    #pragma unroll
    for (int i = 0; i < 2; i++)
        #pragma unroll
        for (int hf = 0; hf < 2; hf++) {
            int row = i * 16 + l2 + hf * 8;
            float m = fmaxf(fmaxf(acc[i][0][2 * hf], acc[i][0][2 * hf + 1]),
                            fmaxf(acc[i][1][2 * hf], acc[i][1][2 * hf + 1]));
            m = fmaxf(m, __shfl_xor_sync(0xffffffff, m, 1));
            m = fmaxf(m, __shfl_xor_sync(0xffffffff, m, 2));
            if (l3 == 0) redM[row][wn] = m;
        }
    __syncthreads();
    #pragma unroll
    for (int i = 0; i < 2; i++)
        #pragma unroll
        for (int hf = 0; hf < 2; hf++) {
            int row = i * 16 + l2 + hf * 8;
            float m = redM[row][0];
            #pragma unroll
            for (int w2 = 1; w2 < 8; w2++) m = fmaxf(m, redM[row][w2]);
            float s = 0.0f;
            #pragma unroll
            for (int j = 0; j < 2; j++) {
                acc[i][j][2 * hf]     = expf(acc[i][j][2 * hf] - m);
                acc[i][j][2 * hf + 1] = expf(acc[i][j][2 * hf + 1] - m);
                s += acc[i][j][2 * hf] + acc[i][j][2 * hf + 1];
            }
            s += __shfl_xor_sync(0xffffffff, s, 1);
            s += __shfl_xor_sync(0xffffffff, s, 2);
            if (l3 == 0) redS[row][wn] = s;
        }
    __syncthreads();
    #pragma unroll
    for (int i = 0; i < 2; i++)
        #pragma unroll
        for (int hf = 0; hf < 2; hf++) {
            int row = i * 16 + l2 + hf * 8;
            float ssum = redS[row][0];
            #pragma unroll
            for (int w2 = 1; w2 < 8; w2++) ssum += redS[row][w2];
            float inv = 1.0f / ssum;
            #pragma unroll
            for (int j = 0; j < 2; j++) {
                int col = wn * 16 + j * 8 + 2 * l3;
                Qsp[row * APAD + col]     = split2f(acc[i][j][2 * hf] * inv);
                Qsp[row * APAD + col + 1] = split2f(acc[i][j][2 * hf + 1] * inv);
            }
        }
    CP_WAIT(0);
    __syncthreads();

    float out[2][2][4] = {};
    #pragma unroll 4
    for (int ks = 0; ks < T; ks += 8) {
        unsigned ah[2][4], al[2][4], bh[2][2], bl[2][2];
        #pragma unroll
        for (int i = 0; i < 2; i++) {
            int m0 = i * 16;
            float2 v0 = Qsp[(m0 + l2) * APAD + ks + l3];
            float2 v1 = Qsp[(m0 + l2 + 8) * APAD + ks + l3];
            float2 v2 = Qsp[(m0 + l2) * APAD + ks + l3 + 4];
            float2 v3 = Qsp[(m0 + l2 + 8) * APAD + ks + l3 + 4];
            ah[i][0] = __float_as_uint(v0.x); al[i][0] = __float_as_uint(v0.y);
            ah[i][1] = __float_as_uint(v1.x); al[i][1] = __float_as_uint(v1.y);
            ah[i][2] = __float_as_uint(v2.x); al[i][2] = __float_as_uint(v2.y);
            ah[i][3] = __float_as_uint(v3.x); al[i][3] = __float_as_uint(v3.y);
        }
        #pragma unroll
        for (int j = 0; j < 2; j++) {
            int n0 = wn * 16 + j * 8;
            split2(Kbuf[(ks + l3) * APAD + n0 + l2],     bh[j][0], bl[j][0]);
            split2(Kbuf[(ks + l3 + 4) * APAD + n0 + l2], bh[j][1], bl[j][1]);
        }
        #pragma unroll
        for (int i = 0; i < 2; i++)
            #pragma unroll
            for (int j = 0; j < 2; j++)
                mma_tf32(out[i][j], ah[i], bh[j]);
        #pragma unroll
        for (int i = 0; i < 2; i++)
            #pragma unroll
            for (int j = 0; j < 2; j++)
                mma_tf32(out[i][j], ah[i], bl[j]);
        #pragma unroll
        for (int i = 0; i < 2; i++)
            #pragma unroll
            for (int j = 0; j < 2; j++)
                mma_tf32(out[i][j], al[i], bh[j]);
    }

    float* Og = O + ((size_t)bb * T + qbase) * D + h * DK;
    #pragma unroll
    for (int i = 0; i < 2; i++)
        #pragma unroll
        for (int j = 0; j < 2; j++) {
            int r = i * 16 + l2;
            int c = wn * 16 + j * 8 + 2 * l3;
            *(float2*)(Og + (size_t)r * D + c) = make_float2(out[i][j][0], out[i][j][1]);
            *(float2*)(Og + (size_t)(r + 8) * D + c) = make_float2(out[i][j][2], out[i][j][3]);
        }
}

#define ATTN_SMEM ((QR * APAD * 2 + 128 * APAD) * 4)

// ---------------- warp helpers ----------------------------------------------
__device__ __forceinline__ float warp_sum(float v) {
    #pragma unroll
    for (int o = 16; o > 0; o >>= 1) v += __shfl_xor_sync(0xffffffff, v, o);
    return v;
}
__device__ __forceinline__ float warp_max(float v) {
    #pragma unroll
    for (int o = 16; o > 0; o >>= 1) v = fmaxf(v, __shfl_xor_sync(0xffffffff, v, o));
    return v;
}

// ---------------- LayerNorm kernels ------------------------------------------
__global__ void add_pos_ln_kernel(const float* __restrict__ qe, const float* __restrict__ ae,
                                  const float* __restrict__ pos,
                                  const float* __restrict__ w, const float* __restrict__ b,
                                  float* __restrict__ out) {
    int row = blockIdx.x, tid = threadIdx.x;
    int lane = tid & 31, wd = tid >> 5;
    __shared__ float p1[4], p2[4];

    const float* src = (row < 512) ? (qe + (size_t)row * D) : (ae + (size_t)(row - 512) * D);
    float4 xv = ((const float4*)src)[tid];
    float4 pv = ((const float4*)(pos + (size_t)(row % T) * D))[tid];
    float4 v = make_float4(xv.x + pv.x, xv.y + pv.y, xv.z + pv.z, xv.w + pv.w);

    float s = warp_sum(v.x + v.y + v.z + v.w);
    if (lane == 0) p1[wd] = s;
    __syncthreads();
    float mean = (p1[0] + p1[1] + p1[2] + p1[3]) * (1.0f / D);
    float4 d = make_float4(v.x - mean, v.y - mean, v.z - mean, v.w - mean);
    float q = warp_sum(d.x * d.x + d.y * d.y + d.z * d.z + d.w * d.w);
    if (lane == 0) p2[wd] = q;
    __syncthreads();
    float inv = rsqrtf((p2[0] + p2[1] + p2[2] + p2[3]) * (1.0f / D) + 1e-12f);

    float4 wv = ((const float4*)w)[tid];
    float4 bv = ((const float4*)b)[tid];
    ((float4*)(out + (size_t)row * D))[tid] =
        make_float4(wv.x * d.x * inv + bv.x, wv.y * d.y * inv + bv.y,
                    wv.z * d.z * inv + bv.z, wv.w * d.w * inv + bv.w);
}

// x += (sum of 4 partials) + gbias; persist; out = LN(x)*w+b
__global__ void residual_ln4_kernel(float* __restrict__ x, const float* __restrict__ yp,
                                    const float* __restrict__ gbias,
                                    float* __restrict__ out,
                                    const float* __restrict__ w, const float* __restrict__ b) {
    int row = blockIdx.x, tid = threadIdx.x;
    int lane = tid & 31, wd = tid >> 5;
    __shared__ float p1[4], p2[4];

    float4 v = ((const float4*)(x + (size_t)row * D))[tid];
    #pragma unroll
    for (int p = 0; p < 4; p++) {
        float4 yv = ((const float4*)(yp + (size_t)p * ND + (size_t)row * D))[tid];
        v.x += yv.x; v.y += yv.y; v.z += yv.z; v.w += yv.w;
    }
    float4 gb = ((const float4*)gbias)[tid];
    v.x += gb.x; v.y += gb.y; v.z += gb.z; v.w += gb.w;
    ((float4*)(x + (size_t)row * D))[tid] = v;

    float s = warp_sum(v.x + v.y + v.z + v.w);
    if (lane == 0) p1[wd] = s;
    __syncthreads();
    float mean = (p1[0] + p1[1] + p1[2] + p1[3]) * (1.0f / D);
    float4 d = make_float4(v.x - mean, v.y - mean, v.z - mean, v.w - mean);
    float q = warp_sum(d.x * d.x + d.y * d.y + d.z * d.z + d.w * d.w);
    if (lane == 0) p2[wd] = q;
    __syncthreads();
    float inv = rsqrtf((p2[0] + p2[1] + p2[2] + p2[3]) * (1.0f / D) + 1e-12f);

    float4 wv = ((const float4*)w)[tid];
    float4 bv = ((const float4*)b)[tid];
    ((float4*)(out + (size_t)row * D))[tid] =
        make_float4(wv.x * d.x * inv + bv.x, wv.y * d.y * inv + bv.y,
                    wv.z * d.z * inv + bv.z, wv.w * d.w * inv + bv.w);
}

// ---------------- sim head helpers ------------------------------------------
__global__ void edot_kernel(const float* __restrict__ X, const float* __restrict__ E,
                            float* __restrict__ out) {
    int row = blockIdx.x;
    int tid = threadIdx.x;
    __shared__ float red[NC * 256];
    float acc[NC] = {};
    for (int d = tid; d < D; d += 256) {
        float x = X[(size_t)row * D + d];
        #pragma unroll
        for (int c = 0; c < NC; c++) acc[c] += x * E[(size_t)c * D + d];
    }
    #pragma unroll
    for (int c = 0; c < NC; c++) red[c * 256 + tid] = acc[c];
    __syncthreads();
    for (int off = 128; off > 0; off >>= 1) {
        if (tid < off) {
            #pragma unroll
            for (int c = 0; c < NC; c++) red[c * 256 + tid] += red[c * 256 + tid + off];
        }
        __syncthreads();
    }
    if (tid < NC) out[(size_t)row * NC + tid] = red[tid * 256];
}

__global__ void gram_kernel(const float* __restrict__ E, float* __restrict__ G) {
    int i = threadIdx.x;
    if (i < NC * NC) {
        int c = i / NC, c2 = i % NC;
        float s = 0.0f;
        for (int d = 0; d < D; d++) s += E[(size_t)c * D + d] * E[(size_t)c2 * D + d];
        G[i] = s;
    }
}

__global__ void sim_attn_kernel(const float* __restrict__ QK, const float* __restrict__ QK2,
                                const float* __restrict__ qa,
                                const float* __restrict__ aq, const float* __restrict__ Eq,
                                const float* __restrict__ Ek, const float* __restrict__ G,
                                float* __restrict__ P, float* __restrict__ Wout) {
    int t = blockIdx.x, b = blockIdx.y;
    int s = threadIdx.x;
    int lane = s & 31, wd = s >> 5;
    __shared__ float g[NC * NC];
    __shared__ float part[4];
    __shared__ float pv[T];
    if (s < NC * NC) g[s] = G[s];
    __syncthreads();

    float f1[NC], f2[NC];
    const float* r1 = qa + (((size_t)b * T + t) * T + s) * NC;
    const float* r2 = aq + (((size_t)b * T + s) * T + t) * NC;
    #pragma unroll
    for (int c = 0; c < NC; c++) { f1[c] = r1[c]; f2[c] = r2[c]; }

    size_t qkidx = ((size_t)b * T + t) * T + s;
    float sc = QK[qkidx] + QK2[qkidx];
    const float* eq = Eq + ((size_t)b * T + t) * NC;
    const float* ek = Ek + ((size_t)b * T + s) * NC;
    #pragma unroll
    for (int c = 0; c < NC; c++) sc += f1[c] * ek[c] + f2[c] * eq[c];
    #pragma unroll
    for (int c = 0; c < NC; c++)
        #pragma unroll
        for (int c2 = 0; c2 < NC; c2++)
            sc += f1[c] * g[c * NC + c2] * f2[c2];

    float m = warp_max(sc);
    if (lane == 0) part[wd] = m;
    __syncthreads();
    float m1 = fmaxf(fmaxf(part[0], part[1]), fmaxf(part[2], part[3]));
    float e1 = expf(sc - m1);
    float ssum = warp_sum(e1);
    if (lane == 0) part[wd] = ssum;
    __syncthreads();
    float p = e1 / (part[0] + part[1] + part[2] + part[3]);

    float l = 1000.0f * p;
    m = warp_max(l);
    __syncthreads();
    if (lane == 0) part[wd] = m;
    __syncthreads();
    float m2 = fmaxf(fmaxf(part[0], part[1]), fmaxf(part[2], part[3]));
    float e2 = expf(l - m2);
    ssum = warp_sum(e2);
    __syncthreads();
    if (lane == 0) part[wd] = ssum;
    __syncthreads();
    float p2 = e2 / (part[0] + part[1] + part[2] + part[3]);
    p2 = fminf(fmaxf(p2, 0.0f), 1.0f);

    P[((size_t)b * T + t) * T + s] = p2;
    pv[s] = p2;
    __syncthreads();

    #pragma unroll
    for (int c = 0; c < NC; c++) {
        float v = warp_sum(pv[s] * f2[c]);
        __syncthreads();
        if (lane == 0) part[wd] = v;
        __syncthreads();
        if (s == 0) Wout[((size_t)b * T + t) * NC + c] = part[0] + part[1] + part[2] + part[3];
    }
}

__global__ void final_kernel(const float* __restrict__ pk, const float* __restrict__ pk2,
                             const float* __restrict__ Wm,
                             const float* __restrict__ E, const float* __restrict__ clsw,
                             const float* __restrict__ clsb, float* __restrict__ out) {
    int b = blockIdx.x;
    int d = threadIdx.x;
    __shared__ float wm[NC];
    __shared__ float red[512];

    if (d < NC) {
        float s = 0.0f;
        for (int t = 0; t < T; t++) s += Wm[((size_t)b * T + t) * NC + d];
        wm[d] = s * (1.0f / T);
    }
    __syncthreads();

    float s = 0.0f;
    for (int t = 0; t < T; t++)
        s += pk[((size_t)b * T + t) * D + d] + pk2[((size_t)b * T + t) * D + d];
    s *= (1.0f / T);
    #pragma unroll
    for (int c = 0; c < NC; c++) s += wm[c] * E[(size_t)c * D + d];

    for (int j = 0; j < 3; j++) {
        red[d] = s * clsw[(size_t)d * 3 + j];
        __syncthreads();
        for (int off = 256; off > 0; off >>= 1) { if (d < off) red[d] += red[d + off]; __syncthreads(); }
        if (d == 0) out[b * 3 + j] = red[0] + clsb[j];
        __syncthreads();
    }
}

// ---------------- host orchestration ----------------------------------------
static inline void g_launch(int transB,
                            const float* A0, const float* A1, const float* A2,
                            const float* W0, const float* W1, const float* W2,
                            const float* b0, const float* b1, const float* b2,
                            float* C0, float* C1, float* C2,
                            int M, int N, int K, int lda, int ldb, int ldc,
                            int act, int nH,
                            long long sA, long long hA, long long sB, long long hB,
                            long long sC, long long hC, int zPerSet, int nz) {
    dim3 grid(N / 64, M / 64, nz);
    if (transB)
        gemm_tf32<1><<<grid, 256>>>(A0, A1, A2, W0, W1, W2, b0, b1, b2, C0, C1, C2,
                                    M, N, K, lda, ldb, ldc, act, nH,
                                    sA, hA, sB, hB, sC, hC, zPerSet);
    else
        gemm_tf32<0><<<grid, 256>>>(A0, A1, A2, W0, W1, W2, b0, b1, b2, C0, C1, C2,
                                    M, N, K, lda, ldb, ldc, act, nH,
                                    sA, hA, sB, hB, sC, hC, zPerSet);
}

extern "C" void kernel_launch(void* const* d_in, const int* in_sizes, int n_in,
                              void* d_out, int out_size) {
    const float* q_emb   = (const float*)d_in[0];
    const float* a_emb   = (const float*)d_in[1];
    const float* qa_rel  = (const float*)d_in[2];
    const float* aq_rel  = (const float*)d_in[3];
    const float* conceptE= (const float*)d_in[4];
    const float* pos_emb = (const float*)d_in[5];
    const float* pe_w    = (const float*)d_in[6];
    const float* pe_b    = (const float*)d_in[7];
    const float* Wq      = (const float*)d_in[8];
    const float* bq      = (const float*)d_in[9];
    const float* Wk      = (const float*)d_in[10];
    const float* bk      = (const float*)d_in[11];
    const float* Wv      = (const float*)d_in[12];
    const float* bv      = (const float*)d_in[13];
    const float* Wo      = (const float*)d_in[14];
    const float* bo      = (const float*)d_in[15];
    const float* ff1w    = (const float*)d_in[16];
    const float* ff1b    = (const float*)d_in[17];
    const float* ff2w    = (const float*)d_in[18];
    const float* ff2b    = (const float*)d_in[19];
    const float* lninw   = (const float*)d_in[20];
    const float* lninb   = (const float*)d_in[21];
    const float* lnoutw  = (const float*)d_in[22];
    const float* lnoutb  = (const float*)d_in[23];
    const float* simWq   = (const float*)d_in[24];
    const float* simbq   = (const float*)d_in[25];
    const float* simWk   = (const float*)d_in[26];
    const float* simbk   = (const float*)d_in[27];
    const float* clsw    = (const float*)d_in[28];
    const float* clsb    = (const float*)d_in[29];
    float* out = (float*)d_out;

    float* base = nullptr;
    cudaGetSymbolAddress((void**)&base, g_scratch);

    float* X   = base + OFF_X;
    float* Qb  = base + OFF_Q;
    float* Kb  = base + OFF_K;
    float* Vb  = base + OFF_V;
    float* T0  = base + OFF_T0;
    float* TP  = base + OFF_TP;
    float* Hb  = base + OFF_H;
    float* FFN = base + OFF_FFN;
    float* QKb = base + OFF_QK;
    float* QK2b= base + OFF_QK2;
    float* Pb  = base + OFF_P;
    float* EQb = base + OFF_EQ;
    float* EKb = base + OFF_EK;
    float* Gb  = base + OFF_G;
    float* Wb  = base + OFF_W;
    float* PKb = base + OFF_PK;
    float* PK2b= base + OFF_PK2;

    cudaFuncSetAttribute(fused_attn, cudaFuncAttributeMaxDynamicSharedMemorySize, ATTN_SMEM);
    cudaFuncSetAttribute(gemm128, cudaFuncAttributeMaxDynamicSharedMemorySize, SM128_BYTES);

    add_pos_ln_kernel<<<M2, 128>>>(q_emb, a_emb, pos_emb, pe_w, pe_b, X);

    for (int i = 0; i < NL; i++) {
        const float* wq = Wq + (size_t)i * D * D;
        const float* wk = Wk + (size_t)i * D * D;
        const float* wv = Wv + (size_t)i * D * D;
        const float* wo = Wo + (size_t)i * D * D;

        // fused QKV: grid (8, 8, 3) = 192 CTAs, 128x64 tiles
        gemm128<<<dim3(8, 8, 3), 256, SM128_BYTES>>>(
            X, X, X, wq, wk, wv,
            bq + (size_t)i * D, bk + (size_t)i * D, bv + (size_t)i * D,
            Qb, Kb, Vb, M2, D, D, D, D, D, 0, 0, 0, 0, 1);

        fused_attn<<<dim3(4, 32), 256, ATTN_SMEM>>>(Qb, Kb, Vb, T0);

        // output projection split-K=4 (grid 8x8x4 = 256), bias in combine
        gemm128<<<dim3(8, 8, 4), 256, SM128_BYTES>>>(
            T0, 0, 0, wo, 0, 0, 0, 0, 0, TP, 0, 0,
            M2, D, 128, D, D, D, 0,
            128, (long long)128 * D, ND, 4);

        residual_ln4_kernel<<<M2, 128>>>(X, TP, bo + (size_t)i * D, Hb,
                                         lninw + (size_t)i * D, lninb + (size_t)i * D);

        // ff1 (grid 32x8 = 256, gelu)
        gemm128<<<dim3(32, 8, 1), 256, SM128_BYTES>>>(
            Hb, 0, 0, ff1w + (size_t)i * D * DFF, 0, 0,
            ff1b + (size_t)i * DFF, 0, 0, FFN, 0, 0,
            M2, DFF, D, D, DFF, DFF, 1, 0, 0, 0, 1);

        // ff2 split-K=4 (grid 8x8x4 = 256), bias in combine
        gemm128<<<dim3(8, 8, 4), 256, SM128_BYTES>>>(
            FFN, 0, 0, ff2w + (size_t)i * DFF * D, 0, 0, 0, 0, 0, TP, 0, 0,
            M2, D, 512, DFF, D, D, 0,
            512, (long long)512 * D, ND, 4);

        residual_ln4_kernel<<<M2, 128>>>(X, TP, ff2b + (size_t)i * D, X,
                                         lnoutw + (size_t)i * D, lnoutb + (size_t)i * D);
    }

    // --- sim head (64x64 path) ---
    g_launch(0, X, X + (size_t)(M2 / 2) * D, 0, simWq, simWk, 0, simbq, simbk, 0, Qb, Kb, 0,
             M2 / 2, D, D, D, D, D, 0, 1, 0, 0, 0, 0, 0, 0, 1, 2);

    edot_kernel<<<M2 / 2, 256>>>(Qb, conceptE, EQb);
    edot_kernel<<<M2 / 2, 256>>>(Kb, conceptE, EKb);
    gram_kernel<<<1, 32>>>(conceptE, Gb);

    g_launch(1, Qb, Qb + 256, 0, Kb, Kb + 256, 0, 0, 0, 0, QKb, QK2b, 0,
             T, T, 256, D, D, T, 0, 1,
             (long long)T * D, 0, (long long)T * D, 0, (long long)T * T, 0, 4, 8);

    sim_attn_kernel<<<dim3(T, Bb), 128>>>(QKb, QK2b, qa_rel, aq_rel, EQb, EKb, Gb, Pb, Wb);

    g_launch(0, Pb, Pb + 64, 0, Kb, Kb + (size_t)64 * D, 0, 0, 0, 0, PKb, PK2b, 0,
             T, D, 64, T, D, D, 0, 1,
             (long long)T * T, 0, (long long)T * D, 0, (long long)T * D, 0, 4, 8);

    final_kernel<<<Bb, 512>>>(PKb, PK2b, Wb, conceptE, clsw, clsb, out);
}

// round 16
// speedup vs baseline: 1.5581x; 1.0407x over previous
#include <cuda_runtime.h>
#include <cuda_bf16.h>
#include <math.h>

// Problem constants
#define Bb   4
#define T    128
#define D    512
#define Hh   4
#define DK   128
#define NL   4
#define DFF  2048
#define NC   5

#define M2   1024
#define ND   (M2*D)

// ---------------- scratch ----------------------------------------------------
#define OFF_X   0
#define OFF_Q   (1*ND)
#define OFF_K   (2*ND)
#define OFF_V   (3*ND)
#define OFF_T0  (4*ND)
#define OFF_TP  (5*ND)              // 4 contiguous split-K partials: 5..9 ND
#define OFF_H   (9*ND)
#define OFF_FFN (10*ND)             // M2*DFF = 4*ND -> ..14 ND
#define OFF_QK  (14*ND)
#define OFF_P   (OFF_QK + 65536)
#define OFF_EQ  (OFF_P + 65536)
#define OFF_EK  (OFF_EQ + 2560)
#define OFF_G   (OFF_EK + 2560)
#define OFF_W   (OFF_G + 32)
#define OFF_PK  (OFF_W + 2560)
#define OFF_QK2 (OFF_PK + 262144)
#define OFF_PK2 (OFF_QK2 + 65536)
#define SCRATCH_TOTAL (OFF_PK2 + 262144)

__device__ float g_scratch[SCRATCH_TOTAL];

__device__ __forceinline__ float gelu_f(float x) {
    return 0.5f * x * (1.0f + erff(x * 0.7071067811865475f));
}

// ---------------- tf32 / mma / cp.async helpers ------------------------------
__device__ __forceinline__ unsigned f2tf32(float x) {
    unsigned r;
    asm("cvt.rna.tf32.f32 %0, %1;" : "=r"(r) : "f"(x));
    return r;
}
__device__ __forceinline__ void split2(float x, unsigned& hi, unsigned& lo) {
    hi = f2tf32(x);
    lo = f2tf32(x - __uint_as_float(hi));
}
__device__ __forceinline__ float2 split2f(float x) {
    unsigned h, l;
    split2(x, h, l);
    return make_float2(__uint_as_float(h), __uint_as_float(l));
}
__device__ __forceinline__ void mma_tf32(float* c, const unsigned* a, const unsigned* b) {
    asm volatile(
        "mma.sync.aligned.m16n8k8.row.col.f32.tf32.tf32.f32 "
        "{%0,%1,%2,%3},{%4,%5,%6,%7},{%8,%9},{%0,%1,%2,%3};"
        : "+f"(c[0]), "+f"(c[1]), "+f"(c[2]), "+f"(c[3])
        : "r"(a[0]), "r"(a[1]), "r"(a[2]), "r"(a[3]), "r"(b[0]), "r"(b[1]));
}
__device__ __forceinline__ void cp16(void* s, const void* g) {
    unsigned sa = (unsigned)__cvta_generic_to_shared(s);
    asm volatile("cp.async.cg.shared.global [%0], [%1], 16;\n" :: "r"(sa), "l"(g) : "memory");
}
#define CP_COMMIT() asm volatile("cp.async.commit_group;\n" ::: "memory")
#define CP_WAIT(n)  asm volatile("cp.async.wait_group %0;\n" :: "n"(n) : "memory")

// ---------------- 64x64 3xTF32 GEMM (sim head), BK=32, 3-stage ---------------
#define PADK 36
#define PADN 72

template<int TRANSB>
__global__ __launch_bounds__(256, 2)
void gemm_tf32(const float* __restrict__ A0, const float* __restrict__ A1, const float* __restrict__ A2,
               const float* __restrict__ W0, const float* __restrict__ W1, const float* __restrict__ W2,
               const float* __restrict__ bias0, const float* __restrict__ bias1, const float* __restrict__ bias2,
               float* __restrict__ C0, float* __restrict__ C1, float* __restrict__ C2,
               int M, int N, int K, int lda, int ldb, int ldc,
               int act, int nH,
               long long sA, long long hA, long long sB, long long hB,
               long long sC, long long hC, int zPerSet) {
    int z = blockIdx.z;
    int set = z / zPerSet;
    int zz = z % zPerSet;
    int bb = zz / nH, hh = zz % nH;

    const float* A  = (set == 0) ? A0 : (set == 1 ? A1 : A2);
    const float* Bm = (set == 0) ? W0 : (set == 1 ? W1 : W2);
    const float* bias = (set == 0) ? bias0 : (set == 1 ? bias1 : bias2);
    float* C = (set == 0) ? C0 : (set == 1 ? C1 : C2);
    A  += bb * sA + hh * hA;
    Bm += bb * sB + hh * hB;
    C  += bb * sC + hh * hC;

    __shared__ float As[3][64][PADK];
    constexpr int BR = TRANSB ? 64 : 32;
    constexpr int BC = TRANSB ? PADK : PADN;
    __shared__ float Bs[3][BR][BC];

    int tid = threadIdx.x;
    int lane = tid & 31, wid = tid >> 5;
    int wm = wid & 1, wn = wid >> 1;
    int l3 = lane & 3, l2 = lane >> 2;

    int bm = blockIdx.y * 64;
    int bn = blockIdx.x * 64;

    int ar = tid >> 2, ak = (tid & 3) * 4;
    int nbr = tid >> 4, nbc = (tid & 15) * 4;

    float acc[2][2][4] = {};

    int nk = K / 32;

    #pragma unroll
    for (int p = 0; p < 2; p++) {
        int k0 = p * 32;
        cp16(&As[p][ar][ak],      A + (size_t)(bm + ar) * lda + k0 + ak);
        cp16(&As[p][ar][ak + 16], A + (size_t)(bm + ar) * lda + k0 + 16 + ak);
        if (TRANSB) {
            cp16(&Bs[p][ar][ak],      Bm + (size_t)(bn + ar) * ldb + k0 + ak);
            cp16(&Bs[p][ar][ak + 16], Bm + (size_t)(bn + ar) * ldb + k0 + 16 + ak);
        } else {
            cp16(&Bs[p][nbr][nbc],      Bm + (size_t)(k0 + nbr) * ldb + bn + nbc);
            cp16(&Bs[p][nbr + 16][nbc], Bm + (size_t)(k0 + nbr + 16) * ldb + bn + nbc);
        }
        CP_COMMIT();
    }

    for (int kt = 0; kt < nk; kt++) {
        CP_WAIT(1);
        __syncthreads();
        int st = kt % 3;
        if (kt + 2 < nk) {
            int ns = (kt + 2) % 3;
            int k0 = (kt + 2) * 32;
            cp16(&As[ns][ar][ak],      A + (size_t)(bm + ar) * lda + k0 + ak);
            cp16(&As[ns][ar][ak + 16], A + (size_t)(bm + ar) * lda + k0 + 16 + ak);
            if (TRANSB) {
                cp16(&Bs[ns][ar][ak],      Bm + (size_t)(bn + ar) * ldb + k0 + ak);
                cp16(&Bs[ns][ar][ak + 16], Bm + (size_t)(bn + ar) * ldb + k0 + 16 + ak);
            } else {
                cp16(&Bs[ns][nbr][nbc],      Bm + (size_t)(k0 + nbr) * ldb + bn + nbc);
                cp16(&Bs[ns][nbr + 16][nbc], Bm + (size_t)(k0 + nbr + 16) * ldb + bn + nbc);
            }
        }
        CP_COMMIT();

        #pragma unroll
        for (int ks = 0; ks < 32; ks += 8) {
            unsigned ah[2][4], al[2][4], bh[2][2], bl[2][2];
            #pragma unroll
            for (int i = 0; i < 2; i++) {
                int m0 = wm * 32 + i * 16;
                split2(As[st][m0 + l2][ks + l3],         ah[i][0], al[i][0]);
                split2(As[st][m0 + l2 + 8][ks + l3],     ah[i][1], al[i][1]);
                split2(As[st][m0 + l2][ks + l3 + 4],     ah[i][2], al[i][2]);
                split2(As[st][m0 + l2 + 8][ks + l3 + 4], ah[i][3], al[i][3]);
            }
            #pragma unroll
            for (int j = 0; j < 2; j++) {
                int n0 = wn * 16 + j * 8;
                if (TRANSB) {
                    split2(Bs[st][n0 + l2][ks + l3],     bh[j][0], bl[j][0]);
                    split2(Bs[st][n0 + l2][ks + l3 + 4], bh[j][1], bl[j][1]);
                } else {
                    split2(Bs[st][ks + l3][n0 + l2],     bh[j][0], bl[j][0]);
                    split2(Bs[st][ks + l3 + 4][n0 + l2], bh[j][1], bl[j][1]);
                }
            }
            #pragma unroll
            for (int i = 0; i < 2; i++)
                #pragma unroll
                for (int j = 0; j < 2; j++)
                    mma_tf32(acc[i][j], ah[i], bh[j]);
            #pragma unroll
            for (int i = 0; i < 2; i++)
                #pragma unroll
                for (int j = 0; j < 2; j++)
                    mma_tf32(acc[i][j], ah[i], bl[j]);
            #pragma unroll
            for (int i = 0; i < 2; i++)
                #pragma unroll
                for (int j = 0; j < 2; j++)
                    mma_tf32(acc[i][j], al[i], bh[j]);
        }
    }

    #pragma unroll
    for (int i = 0; i < 2; i++) {
        #pragma unroll
        for (int j = 0; j < 2; j++) {
            int rg = bm + wm * 32 + i * 16 + l2;
            int cg = bn + wn * 16 + j * 8 + 2 * l3;
            float bv0 = bias ? bias[cg] : 0.0f;
            float bv1 = bias ? bias[cg + 1] : 0.0f;
            float v0 = acc[i][j][0] + bv0, v1 = acc[i][j][1] + bv1;
            float v2 = acc[i][j][2] + bv0, v3 = acc[i][j][3] + bv1;
            if (act) { v0 = gelu_f(v0); v1 = gelu_f(v1); v2 = gelu_f(v2); v3 = gelu_f(v3); }
            *(float2*)(C + (size_t)rg * ldc + cg) = make_float2(v0, v1);
            *(float2*)(C + (size_t)(rg + 8) * ldc + cg) = make_float2(v2, v3);
        }
    }
}

// ---------------- 128x128 3xTF32 GEMM (encoder), BK=32, 3-stage --------------
// 8 warps, warp grid 2(m) x 4(n), warp tile 64x32. non-trans B only.
#define PBN 136
#define SMBIG_FLOATS (3 * 128 * PADK + 3 * 32 * PBN)
#define SMBIG_BYTES  (SMBIG_FLOATS * 4)

__global__ __launch_bounds__(256, 1)
void gemm_big(const float* __restrict__ A0, const float* __restrict__ A1, const float* __restrict__ A2,
              const float* __restrict__ W0, const float* __restrict__ W1, const float* __restrict__ W2,
              const float* __restrict__ bias0, const float* __restrict__ bias1, const float* __restrict__ bias2,
              float* __restrict__ C0, float* __restrict__ C1, float* __restrict__ C2,
              int M, int N, int K, int lda, int ldb, int ldc,
              int act,
              long long sA, long long sB, long long sC, int zPerSet) {
    int z = blockIdx.z;
    int set = z / zPerSet;
    int zz = z % zPerSet;

    const float* A  = (set == 0) ? A0 : (set == 1 ? A1 : A2);
    const float* Bm = (set == 0) ? W0 : (set == 1 ? W1 : W2);
    const float* bias = (set == 0) ? bias0 : (set == 1 ? bias1 : bias2);
    float* C = (set == 0) ? C0 : (set == 1 ? C1 : C2);
    A  += zz * sA;
    Bm += zz * sB;
    C  += zz * sC;

    extern __shared__ float sm[];
    float* Asm = sm;                      // [3][128][PADK]
    float* Bsm = sm + 3 * 128 * PADK;     // [3][32][PBN]

    int tid = threadIdx.x;
    int lane = tid & 31, wid = tid >> 5;
    int wm = wid >> 2, wn = wid & 3;      // 2m x 4n; warp tile 64x32
    int l3 = lane & 3, l2 = lane >> 2;

    int bm = blockIdx.y * 128;
    int bn = blockIdx.x * 128;

    float acc[4][4][4] = {};
    int nk = K / 32;

    // loaders: A 128 rows x 8 quads = 1024; B 32 rows x 32 quads = 1024; 4 each/thread
    #pragma unroll
    for (int p = 0; p < 2; p++) {
        int k0 = p * 32;
        float* As = Asm + p * 128 * PADK;
        float* Bs = Bsm + p * 32 * PBN;
        #pragma unroll
        for (int t = 0; t < 4; t++) {
            int q = tid + t * 256;
            int r = q >> 3, kq = (q & 7) * 4;
            cp16(&As[r * PADK + kq], A + (size_t)(bm + r) * lda + k0 + kq);
        }
        #pragma unroll
        for (int t = 0; t < 4; t++) {
            int q = tid + t * 256;
            int r = q >> 5, nc = (q & 31) * 4;
            cp16(&Bs[r * PBN + nc], Bm + (size_t)(k0 + r) * ldb + bn + nc);
        }
        CP_COMMIT();
    }

    for (int kt = 0; kt < nk; kt++) {
        CP_WAIT(1);
        __syncthreads();
        int st = kt % 3;
        if (kt + 2 < nk) {
            int ns = (kt + 2) % 3;
            int k0 = (kt + 2) * 32;
            float* As = Asm + ns * 128 * PADK;
            float* Bs = Bsm + ns * 32 * PBN;
            #pragma unroll
            for (int t = 0; t < 4; t++) {
                int q = tid + t * 256;
                int r = q >> 3, kq = (q & 7) * 4;
                cp16(&As[r * PADK + kq], A + (size_t)(bm + r) * lda + k0 + kq);
            }
            #pragma unroll
            for (int t = 0; t < 4; t++) {
                int q = tid + t * 256;
                int r = q >> 5, nc = (q & 31) * 4;
                cp16(&Bs[r * PBN + nc], Bm + (size_t)(k0 + r) * ldb + bn + nc);
            }
        }
        CP_COMMIT();

        const float* As = Asm + st * 128 * PADK;
        const float* Bs = Bsm + st * 32 * PBN;

        #pragma unroll
        for (int ks = 0; ks < 32; ks += 8) {
            unsigned ah[4][4], al[4][4], bh[4][2], bl[4][2];
            #pragma unroll
            for (int i = 0; i < 4; i++) {
                int m0 = wm * 64 + i * 16;
                split2(As[(m0 + l2) * PADK + ks + l3],         ah[i][0], al[i][0]);
                split2(As[(m0 + l2 + 8) * PADK + ks + l3],     ah[i][1], al[i][1]);
                split2(As[(m0 + l2) * PADK + ks + l3 + 4],     ah[i][2], al[i][2]);
                split2(As[(m0 + l2 + 8) * PADK + ks + l3 + 4], ah[i][3], al[i][3]);
            }
            #pragma unroll
            for (int j = 0; j < 4; j++) {
                int n0 = wn * 32 + j * 8;
                split2(Bs[(ks + l3) * PBN + n0 + l2],     bh[j][0], bl[j][0]);
                split2(Bs[(ks + l3 + 4) * PBN + n0 + l2], bh[j][1], bl[j][1]);
            }
            #pragma unroll
            for (int i = 0; i < 4; i++)
                #pragma unroll
                for (int j = 0; j < 4; j++)
                    mma_tf32(acc[i][j], ah[i], bh[j]);
            #pragma unroll
            for (int i = 0; i < 4; i++)
                #pragma unroll
                for (int j = 0; j < 4; j++)
                    mma_tf32(acc[i][j], ah[i], bl[j]);
            #pragma unroll
            for (int i = 0; i < 4; i++)
                #pragma unroll
                for (int j = 0; j < 4; j++)
                    mma_tf32(acc[i][j], al[i], bh[j]);
        }
    }

    #pragma unroll
    for (int i = 0; i < 4; i++) {
        #pragma unroll
        for (int j = 0; j < 4; j++) {
            int rg = bm + wm * 64 + i * 16 + l2;
            int cg = bn + wn * 32 + j * 8 + 2 * l3;
            float bv0 = bias ? bias[cg] : 0.0f;
            float bv1 = bias ? bias[cg + 1] : 0.0f;
            float v0 = acc[i][j][0] + bv0, v1 = acc[i][j][1] + bv1;
            float v2 = acc[i][j][2] + bv0, v3 = acc[i][j][3] + bv1;
            if (act) { v0 = gelu_f(v0); v1 = gelu_f(v1); v2 = gelu_f(v2); v3 = gelu_f(v3); }
            *(float2*)(C + (size_t)rg * ldc + cg) = make_float2(v0, v1);
            *(float2*)(C + (size_t)(rg + 8) * ldc + cg) = make_float2(v2, v3);
        }
    }
}

// ---------------- fused attention: Qsp-only smem (2 CTAs/SM) -----------------
#define APAD 132
#define QR 32
__global__ __launch_bounds__(256)
void fused_attn(const float* __restrict__ Q, const float* __restrict__ K,
                const float* __restrict__ V, float* __restrict__ O) {
    extern __shared__ float dyn[];
    float2* Qsp  = (float2*)dyn;                  // [QR][APAD] float2
    float*  Kbuf = dyn + QR * APAD * 2;           // [128][APAD] float
    __shared__ float redM[QR][8];
    __shared__ float redS[QR][8];

    int bz = blockIdx.y;
    int bb = bz >> 2, h = bz & 3;
    int qbase = blockIdx.x * QR;

    int tid = threadIdx.x;
    int lane = tid & 31, wn = tid >> 5;
    int l3 = lane & 3, l2 = lane >> 2;

    const float* Qg = Q + ((size_t)bb * T + qbase) * D + h * DK;
    const float* Kg = K + ((size_t)bb * T) * D + h * DK;
    const float* Vg = V + ((size_t)bb * T) * D + h * DK;

    #pragma unroll
    for (int t = 0; t < 16; t++) {
        int idx = tid + t * 256;
        int r = idx >> 5, c = (idx & 31) * 4;
        cp16(&Kbuf[r * APAD + c], Kg + (size_t)r * D + c);
    }
    CP_COMMIT();

    {
        #pragma unroll
        for (int t = 0; t < 4; t++) {
            int q = tid + t * 256;
            int r = q >> 5, c = (q & 31) * 4;
            float4 v = *(const float4*)(Qg + (size_t)r * D + c);
            Qsp[r * APAD + c]     = split2f(v.x);
            Qsp[r * APAD + c + 1] = split2f(v.y);
            Qsp[r * APAD + c + 2] = split2f(v.z);
            Qsp[r * APAD + c + 3] = split2f(v.w);
        }
    }
    CP_WAIT(0);
    __syncthreads();

    float acc[2][2][4] = {};
    #pragma unroll 4
    for (int ks = 0; ks < DK; ks += 8) {
        unsigned ah[2][4], al[2][4], bh[2][2], bl[2][2];
        #pragma unroll
        for (int i = 0; i < 2; i++) {
            int m0 = i * 16;
            float2 v0 = Qsp[(m0 + l2) * APAD + ks + l3];
            float2 v1 = Qsp[(m0 + l2 + 8) * APAD + ks + l3];
            float2 v2 = Qsp[(m0 + l2) * APAD + ks + l3 + 4];
            float2 v3 = Qsp[(m0 + l2 + 8) * APAD + ks + l3 + 4];
            ah[i][0] = __float_as_uint(v0.x); al[i][0] = __float_as_uint(v0.y);
            ah[i][1] = __float_as_uint(v1.x); al[i][1] = __float_as_uint(v1.y);
            ah[i][2] = __float_as_uint(v2.x); al[i][2] = __float_as_uint(v2.y);
            ah[i][3] = __float_as_uint(v3.x); al[i][3] = __float_as_uint(v3.y);
        }
        #pragma unroll
        for (int j = 0; j < 2; j++) {
            int n0 = wn * 16 + j * 8;
            split2(Kbuf[(n0 + l2) * APAD + ks + l3],     bh[j][0], bl[j][0]);
            split2(Kbuf[(n0 + l2) * APAD + ks + l3 + 4], bh[j][1], bl[j][1]);
        }
        #pragma unroll
        for (int i = 0; i < 2; i++)
            #pragma unroll
            for (int j = 0; j < 2; j++)
                mma_tf32(acc[i][j], ah[i], bh[j]);
        #pragma unroll
        for (int i = 0; i < 2; i++)
            #pragma unroll
            for (int j = 0; j < 2; j++)
                mma_tf32(acc[i][j], ah[i], bl[j]);
        #pragma unroll
        for (int i = 0; i < 2; i++)
            #pragma unroll
            for (int j = 0; j < 2; j++)
                mma_tf32(acc[i][j], al[i], bh[j]);
    }
    __syncthreads();

    #pragma unroll
    for (int t = 0; t < 16; t++) {
        int idx = tid + t * 256;
        int r = idx >> 5, c = (idx & 31) * 4;
        cp16(&Kbuf[r * APAD + c], Vg + (size_t)r * D + c);
    }
    CP_COMMIT();

    const float sc = 0.08838834764831845f;
    #pragma unroll
    for (int i = 0; i < 2; i++)
        #pragma unroll
        for (int j = 0; j < 2; j++)
            #pragma unroll
            for (int q = 0; q < 4; q++) acc[i][j][q] *= sc;

    #pragma unroll
    for (int i = 0; i < 2; i++)
        #pragma unroll
        for (int hf = 0; hf < 2; hf++) {
            int row = i * 16 + l2 + hf * 8;
            float m = fmaxf(fmaxf(acc[i][0][2 * hf], acc[i][0][2 * hf + 1]),
                            fmaxf(acc[i][1][2 * hf], acc[i][1][2 * hf + 1]));
            m = fmaxf(m, __shfl_xor_sync(0xffffffff, m, 1));
            m = fmaxf(m, __shfl_xor_sync(0xffffffff, m, 2));
            if (l3 == 0) redM[row][wn] = m;
        }
    __syncthreads();
    #pragma unroll
    for (int i = 0; i < 2; i++)
        #pragma unroll
        for (int hf = 0; hf < 2; hf++) {
            int row = i * 16 + l2 + hf * 8;
            float m = redM[row][0];
            #pragma unroll
            for (int w2 = 1; w2 < 8; w2++) m = fmaxf(m, redM[row][w2]);
            float s = 0.0f;
            #pragma unroll
            for (int j = 0; j < 2; j++) {
                acc[i][j][2 * hf]     = expf(acc[i][j][2 * hf] - m);
                acc[i][j][2 * hf + 1] = expf(acc[i][j][2 * hf + 1] - m);
                s += acc[i][j][2 * hf] + acc[i][j][2 * hf + 1];
            }
            s += __shfl_xor_sync(0xffffffff, s, 1);
            s += __shfl_xor_sync(0xffffffff, s, 2);
            if (l3 == 0) redS[row][wn] = s;
        }
    __syncthreads();
    #pragma unroll
    for (int i = 0; i < 2; i++)
        #pragma unroll
        for (int hf = 0; hf < 2; hf++) {
            int row = i * 16 + l2 + hf * 8;
            float ssum = redS[row][0];
            #pragma unroll
            for (int w2 = 1; w2 < 8; w2++) ssum += redS[row][w2];
            float inv = 1.0f / ssum;
            #pragma unroll
            for (int j = 0; j < 2; j++) {
                int col = wn * 16 + j * 8 + 2 * l3;
                Qsp[row * APAD + col]     = split2f(acc[i][j][2 * hf] * inv);
                Qsp[row * APAD + col + 1] = split2f(acc[i][j][2 * hf + 1] * inv);
            }
        }
    CP_WAIT(0);
    __syncthreads();

    float out[2][2][4] = {};
    #pragma unroll 4
    for (int ks = 0; ks < T; ks += 8) {
        unsigned ah[2][4], al[2][4], bh[2][2], bl[2][2];
        #pragma unroll
        for (int i = 0; i < 2; i++) {
            int m0 = i * 16;
            float2 v0 = Qsp[(m0 + l2) * APAD + ks + l3];
            float2 v1 = Qsp[(m0 + l2 + 8) * APAD + ks + l3];
            float2 v2 = Qsp[(m0 + l2) * APAD + ks + l3 + 4];
            float2 v3 = Qsp[(m0 + l2 + 8) * APAD + ks + l3 + 4];
            ah[i][0] = __float_as_uint(v0.x); al[i][0] = __float_as_uint(v0.y);
            ah[i][1] = __float_as_uint(v1.x); al[i][1] = __float_as_uint(v1.y);
            ah[i][2] = __float_as_uint(v2.x); al[i][2] = __float_as_uint(v2.y);
            ah[i][3] = __float_as_uint(v3.x); al[i][3] = __float_as_uint(v3.y);
        }
        #pragma unroll
        for (int j = 0; j < 2; j++) {
            int n0 = wn * 16 + j * 8;
            split2(Kbuf[(ks + l3) * APAD + n0 + l2],     bh[j][0], bl[j][0]);
            split2(Kbuf[(ks + l3 + 4) * APAD + n0 + l2], bh[j][1], bl[j][1]);
        }
        #pragma unroll
        for (int i = 0; i < 2; i++)
            #pragma unroll
            for (int j = 0; j < 2; j++)
                mma_tf32(out[i][j], ah[i], bh[j]);
        #pragma unroll
        for (int i = 0; i < 2; i++)
            #pragma unroll
            for (int j = 0; j < 2; j++)
                mma_tf32(out[i][j], ah[i], bl[j]);
        #pragma unroll
        for (int i = 0; i < 2; i++)
            #pragma unroll
            for (int j = 0; j < 2; j++)
                mma_tf32(out[i][j], al[i], bh[j]);
    }

    float* Og = O + ((size_t)bb * T + qbase) * D + h * DK;
    #pragma unroll
    for (int i = 0; i < 2; i++)
        #pragma unroll
        for (int j = 0; j < 2; j++) {
            int r = i * 16 + l2;
            int c = wn * 16 + j * 8 + 2 * l3;
            *(float2*)(Og + (size_t)r * D + c) = make_float2(out[i][j][0], out[i][j][1]);
            *(float2*)(Og + (size_t)(r + 8) * D + c) = make_float2(out[i][j][2], out[i][j][3]);
        }
}

#define ATTN_SMEM ((QR * APAD * 2 + 128 * APAD) * 4)

// ---------------- warp helpers ----------------------------------------------
__device__ __forceinline__ float warp_sum(float v) {
    #pragma unroll
    for (int o = 16; o > 0; o >>= 1) v += __shfl_xor_sync(0xffffffff, v, o);
    return v;
}
__device__ __forceinline__ float warp_max(float v) {
    #pragma unroll
    for (int o = 16; o > 0; o >>= 1) v = fmaxf(v, __shfl_xor_sync(0xffffffff, v, o));
    return v;
}

// ---------------- LayerNorm kernels ------------------------------------------
__global__ void add_pos_ln_kernel(const float* __restrict__ qe, const float* __restrict__ ae,
                                  const float* __restrict__ pos,
                                  const float* __restrict__ w, const float* __restrict__ b,
                                  float* __restrict__ out) {
    int row = blockIdx.x, tid = threadIdx.x;
    int lane = tid & 31, wd = tid >> 5;
    __shared__ float p1[4], p2[4];

    const float* src = (row < 512) ? (qe + (size_t)row * D) : (ae + (size_t)(row - 512) * D);
    float4 xv = ((const float4*)src)[tid];
    float4 pv = ((const float4*)(pos + (size_t)(row % T) * D))[tid];
    float4 v = make_float4(xv.x + pv.x, xv.y + pv.y, xv.z + pv.z, xv.w + pv.w);

    float s = warp_sum(v.x + v.y + v.z + v.w);
    if (lane == 0) p1[wd] = s;
    __syncthreads();
    float mean = (p1[0] + p1[1] + p1[2] + p1[3]) * (1.0f / D);
    float4 d = make_float4(v.x - mean, v.y - mean, v.z - mean, v.w - mean);
    float q = warp_sum(d.x * d.x + d.y * d.y + d.z * d.z + d.w * d.w);
    if (lane == 0) p2[wd] = q;
    __syncthreads();
    float inv = rsqrtf((p2[0] + p2[1] + p2[2] + p2[3]) * (1.0f / D) + 1e-12f);

    float4 wv = ((const float4*)w)[tid];
    float4 bv = ((const float4*)b)[tid];
    ((float4*)(out + (size_t)row * D))[tid] =
        make_float4(wv.x * d.x * inv + bv.x, wv.y * d.y * inv + bv.y,
                    wv.z * d.z * inv + bv.z, wv.w * d.w * inv + bv.w);
}

// x += (sum of 4 partials) + gbias; persist; out = LN(x)*w+b
__global__ void residual_ln4_kernel(float* __restrict__ x, const float* __restrict__ yp,
                                    const float* __restrict__ gbias,
                                    float* __restrict__ out,
                                    const float* __restrict__ w, const float* __restrict__ b) {
    int row = blockIdx.x, tid = threadIdx.x;
    int lane = tid & 31, wd = tid >> 5;
    __shared__ float p1[4], p2[4];

    float4 v = ((const float4*)(x + (size_t)row * D))[tid];
    #pragma unroll
    for (int p = 0; p < 4; p++) {
        float4 yv = ((const float4*)(yp + (size_t)p * ND + (size_t)row * D))[tid];
        v.x += yv.x; v.y += yv.y; v.z += yv.z; v.w += yv.w;
    }
    float4 gb = ((const float4*)gbias)[tid];
    v.x += gb.x; v.y += gb.y; v.z += gb.z; v.w += gb.w;
    ((float4*)(x + (size_t)row * D))[tid] = v;

    float s = warp_sum(v.x + v.y + v.z + v.w);
    if (lane == 0) p1[wd] = s;
    __syncthreads();
    float mean = (p1[0] + p1[1] + p1[2] + p1[3]) * (1.0f / D);
    float4 d = make_float4(v.x - mean, v.y - mean, v.z - mean, v.w - mean);
    float q = warp_sum(d.x * d.x + d.y * d.y + d.z * d.z + d.w * d.w);
    if (lane == 0) p2[wd] = q;
    __syncthreads();
    float inv = rsqrtf((p2[0] + p2[1] + p2[2] + p2[3]) * (1.0f / D) + 1e-12f);

    float4 wv = ((const float4*)w)[tid];
    float4 bv = ((const float4*)b)[tid];
    ((float4*)(out + (size_t)row * D))[tid] =
        make_float4(wv.x * d.x * inv + bv.x, wv.y * d.y * inv + bv.y,
                    wv.z * d.z * inv + bv.z, wv.w * d.w * inv + bv.w);
}

// ---------------- sim head helpers ------------------------------------------
// blocks 0..511: edot for Qs rows; 512..1023: edot for Ks rows; 1024: gram
__global__ void edot_all_kernel(const float* __restrict__ Qs, const float* __restrict__ Ks,
                                const float* __restrict__ E,
                                float* __restrict__ outQ, float* __restrict__ outK,
                                float* __restrict__ G) {
    int blk = blockIdx.x;
    int tid = threadIdx.x;
    if (blk == 1024) {
        if (tid < NC * NC) {
            int c = tid / NC, c2 = tid % NC;
            float s = 0.0f;
            for (int d = 0; d < D; d++) s += E[(size_t)c * D + d] * E[(size_t)c2 * D + d];
            G[tid] = s;
        }
        return;
    }
    const float* X = (blk < 512) ? (Qs + (size_t)blk * D) : (Ks + (size_t)(blk - 512) * D);
    float* outp = (blk < 512) ? (outQ + (size_t)blk * NC) : (outK + (size_t)(blk - 512) * NC);

    __shared__ float red[NC * 256];
    float acc[NC] = {};
    for (int d = tid; d < D; d += 256) {
        float x = X[d];
        #pragma unroll
        for (int c = 0; c < NC; c++) acc[c] += x * E[(size_t)c * D + d];
    }
    #pragma unroll
    for (int c = 0; c < NC; c++) red[c * 256 + tid] = acc[c];
    __syncthreads();
    for (int off = 128; off > 0; off >>= 1) {
        if (tid < off) {
            #pragma unroll
            for (int c = 0; c < NC; c++) red[c * 256 + tid] += red[c * 256 + tid + off];
        }
        __syncthreads();
    }
    if (tid < NC) outp[tid] = red[tid * 256];
}

__global__ void sim_attn_kernel(const float* __restrict__ QK, const float* __restrict__ QK2,
                                const float* __restrict__ qa,
                                const float* __restrict__ aq, const float* __restrict__ Eq,
                                const float* __restrict__ Ek, const float* __restrict__ G,
                                float* __restrict__ P, float* __restrict__ Wout) {
    int t = blockIdx.x, b = blockIdx.y;
    int s = threadIdx.x;
    int lane = s & 31, wd = s >> 5;
    __shared__ float g[NC * NC];
    __shared__ float part[4];
    __shared__ float pv[T];
    if (s < NC * NC) g[s] = G[s];
    __syncthreads();

    float f1[NC], f2[NC];
    const float* r1 = qa + (((size_t)b * T + t) * T + s) * NC;
    const float* r2 = aq + (((size_t)b * T + s) * T + t) * NC;
    #pragma unroll
    for (int c = 0; c < NC; c++) { f1[c] = r1[c]; f2[c] = r2[c]; }

    size_t qkidx = ((size_t)b * T + t) * T + s;
    float sc = QK[qkidx] + QK2[qkidx];
    const float* eq = Eq + ((size_t)b * T + t) * NC;
    const float* ek = Ek + ((size_t)b * T + s) * NC;
    #pragma unroll
    for (int c = 0; c < NC; c++) sc += f1[c] * ek[c] + f2[c] * eq[c];
    #pragma unroll
    for (int c = 0; c < NC; c++)
        #pragma unroll
        for (int c2 = 0; c2 < NC; c2++)
            sc += f1[c] * g[c * NC + c2] * f2[c2];

    float m = warp_max(sc);
    if (lane == 0) part[wd] = m;
    __syncthreads();
    float m1 = fmaxf(fmaxf(part[0], part[1]), fmaxf(part[2], part[3]));
    float e1 = expf(sc - m1);
    float ssum = warp_sum(e1);
    if (lane == 0) part[wd] = ssum;
    __syncthreads();
    float p = e1 / (part[0] + part[1] + part[2] + part[3]);

    float l = 1000.0f * p;
    m = warp_max(l);
    __syncthreads();
    if (lane == 0) part[wd] = m;
    __syncthreads();
    float m2 = fmaxf(fmaxf(part[0], part[1]), fmaxf(part[2], part[3]));
    float e2 = expf(l - m2);
    ssum = warp_sum(e2);
    __syncthreads();
    if (lane == 0) part[wd] = ssum;
    __syncthreads();
    float p2 = e2 / (part[0] + part[1] + part[2] + part[3]);
    p2 = fminf(fmaxf(p2, 0.0f), 1.0f);

    P[((size_t)b * T + t) * T + s] = p2;
    pv[s] = p2;
    __syncthreads();

    #pragma unroll
    for (int c = 0; c < NC; c++) {
        float v = warp_sum(pv[s] * f2[c]);
        __syncthreads();
        if (lane == 0) part[wd] = v;
        __syncthreads();
        if (s == 0) Wout[((size_t)b * T + t) * NC + c] = part[0] + part[1] + part[2] + part[3];
    }
}

__global__ void final_kernel(const float* __restrict__ pk, const float* __restrict__ pk2,
                             const float* __restrict__ Wm,
                             const float* __restrict__ E, const float* __restrict__ clsw,
                             const float* __restrict__ clsb, float* __restrict__ out) {
    int b = blockIdx.x;
    int d = threadIdx.x;
    __shared__ float wm[NC];
    __shared__ float red[512];

    if (d < NC) {
        float s = 0.0f;
        for (int t = 0; t < T; t++) s += Wm[((size_t)b * T + t) * NC + d];
        wm[d] = s * (1.0f / T);
    }
    __syncthreads();

    float s = 0.0f;
    for (int t = 0; t < T; t++)
        s += pk[((size_t)b * T + t) * D + d] + pk2[((size_t)b * T + t) * D + d];
    s *= (1.0f / T);
    #pragma unroll
    for (int c = 0; c < NC; c++) s += wm[c] * E[(size_t)c * D + d];

    for (int j = 0; j < 3; j++) {
        red[d] = s * clsw[(size_t)d * 3 + j];
        __syncthreads();
        for (int off = 256; off > 0; off >>= 1) { if (d < off) red[d] += red[d + off]; __syncthreads(); }
        if (d == 0) out[b * 3 + j] = red[0] + clsb[j];
        __syncthreads();
    }
}

// ---------------- host orchestration ----------------------------------------
static inline void g_launch(int transB,
                            const float* A0, const float* A1, const float* A2,
                            const float* W0, const float* W1, const float* W2,
                            const float* b0, const float* b1, const float* b2,
                            float* C0, float* C1, float* C2,
                            int M, int N, int K, int lda, int ldb, int ldc,
                            int act, int nH,
                            long long sA, long long hA, long long sB, long long hB,
                            long long sC, long long hC, int zPerSet, int nz) {
    dim3 grid(N / 64, M / 64, nz);
    if (transB)
        gemm_tf32<1><<<grid, 256>>>(A0, A1, A2, W0, W1, W2, b0, b1, b2, C0, C1, C2,
                                    M, N, K, lda, ldb, ldc, act, nH,
                                    sA, hA, sB, hB, sC, hC, zPerSet);
    else
        gemm_tf32<0><<<grid, 256>>>(A0, A1, A2, W0, W1, W2, b0, b1, b2, C0, C1, C2,
                                    M, N, K, lda, ldb, ldc, act, nH,
                                    sA, hA, sB, hB, sC, hC, zPerSet);
}

extern "C" void kernel_launch(void* const* d_in, const int* in_sizes, int n_in,
                              void* d_out, int out_size) {
    const float* q_emb   = (const float*)d_in[0];
    const float* a_emb   = (const float*)d_in[1];
    const float* qa_rel  = (const float*)d_in[2];
    const float* aq_rel  = (const float*)d_in[3];
    const float* conceptE= (const float*)d_in[4];
    const float* pos_emb = (const float*)d_in[5];
    const float* pe_w    = (const float*)d_in[6];
    const float* pe_b    = (const float*)d_in[7];
    const float* Wq      = (const float*)d_in[8];
    const float* bq      = (const float*)d_in[9];
    const float* Wk      = (const float*)d_in[10];
    const float* bk      = (const float*)d_in[11];
    const float* Wv      = (const float*)d_in[12];
    const float* bv      = (const float*)d_in[13];
    const float* Wo      = (const float*)d_in[14];
    const float* bo      = (const float*)d_in[15];
    const float* ff1w    = (const float*)d_in[16];
    const float* ff1b    = (const float*)d_in[17];
    const float* ff2w    = (const float*)d_in[18];
    const float* ff2b    = (const float*)d_in[19];
    const float* lninw   = (const float*)d_in[20];
    const float* lninb   = (const float*)d_in[21];
    const float* lnoutw  = (const float*)d_in[22];
    const float* lnoutb  = (const float*)d_in[23];
    const float* simWq   = (const float*)d_in[24];
    const float* simbq   = (const float*)d_in[25];
    const float* simWk   = (const float*)d_in[26];
    const float* simbk   = (const float*)d_in[27];
    const float* clsw    = (const float*)d_in[28];
    const float* clsb    = (const float*)d_in[29];
    float* out = (float*)d_out;

    float* base = nullptr;
    cudaGetSymbolAddress((void**)&base, g_scratch);

    float* X   = base + OFF_X;
    float* Qb  = base + OFF_Q;
    float* Kb  = base + OFF_K;
    float* Vb  = base + OFF_V;
    float* T0  = base + OFF_T0;
    float* TP  = base + OFF_TP;
    float* Hb  = base + OFF_H;
    float* FFN = base + OFF_FFN;
    float* QKb = base + OFF_QK;
    float* QK2b= base + OFF_QK2;
    float* Pb  = base + OFF_P;
    float* EQb = base + OFF_EQ;
    float* EKb = base + OFF_EK;
    float* Gb  = base + OFF_G;
    float* Wb  = base + OFF_W;
    float* PKb = base + OFF_PK;
    float* PK2b= base + OFF_PK2;

    cudaFuncSetAttribute(fused_attn, cudaFuncAttributeMaxDynamicSharedMemorySize, ATTN_SMEM);
    cudaFuncSetAttribute(gemm_big, cudaFuncAttributeMaxDynamicSharedMemorySize, SMBIG_BYTES);

    add_pos_ln_kernel<<<M2, 128>>>(q_emb, a_emb, pos_emb, pe_w, pe_b, X);

    for (int i = 0; i < NL; i++) {
        const float* wq = Wq + (size_t)i * D * D;
        const float* wk = Wk + (size_t)i * D * D;
        const float* wv = Wv + (size_t)i * D * D;
        const float* wo = Wo + (size_t)i * D * D;

        // fused QKV: grid (4, 8, 3) = 96 CTAs, 128x128 tiles
        gemm_big<<<dim3(4, 8, 3), 256, SMBIG_BYTES>>>(
            X, X, X, wq, wk, wv,
            bq + (size_t)i * D, bk + (size_t)i * D, bv + (size_t)i * D,
            Qb, Kb, Vb, M2, D, D, D, D, D, 0, 0, 0, 0, 1);

        fused_attn<<<dim3(4, 32), 256, ATTN_SMEM>>>(Qb, Kb, Vb, T0);

        // output projection split-K=4 (grid 4x8x4 = 128), bias in combine
        gemm_big<<<dim3(4, 8, 4), 256, SMBIG_BYTES>>>(
            T0, 0, 0, wo, 0, 0, 0, 0, 0, TP, 0, 0,
            M2, D, 128, D, D, D, 0,
            128, (long long)128 * D, ND, 4);

        residual_ln4_kernel<<<M2, 128>>>(X, TP, bo + (size_t)i * D, Hb,
                                         lninw + (size_t)i * D, lninb + (size_t)i * D);

        // ff1 (grid 16x8 = 128, gelu)
        gemm_big<<<dim3(16, 8, 1), 256, SMBIG_BYTES>>>(
            Hb, 0, 0, ff1w + (size_t)i * D * DFF, 0, 0,
            ff1b + (size_t)i * DFF, 0, 0, FFN, 0, 0,
            M2, DFF, D, D, DFF, DFF, 1, 0, 0, 0, 1);

        // ff2 split-K=4 (grid 4x8x4 = 128), bias in combine
        gemm_big<<<dim3(4, 8, 4), 256, SMBIG_BYTES>>>(
            FFN, 0, 0, ff2w + (size_t)i * DFF * D, 0, 0, 0, 0, 0, TP, 0, 0,
            M2, D, 512, DFF, D, D, 0,
            512, (long long)512 * D, ND, 4);

        residual_ln4_kernel<<<M2, 128>>>(X, TP, ff2b + (size_t)i * D, X,
                                         lnoutw + (size_t)i * D, lnoutb + (size_t)i * D);
    }

    // --- sim head (64x64 path) ---
    g_launch(0, X, X + (size_t)(M2 / 2) * D, 0, simWq, simWk, 0, simbq, simbk, 0, Qb, Kb, 0,
             M2 / 2, D, D, D, D, D, 0, 1, 0, 0, 0, 0, 0, 0, 1, 2);

    edot_all_kernel<<<1025, 256>>>(Qb, Kb, conceptE, EQb, EKb, Gb);

    g_launch(1, Qb, Qb + 256, 0, Kb, Kb + 256, 0, 0, 0, 0, QKb, QK2b, 0,
             T, T, 256, D, D, T, 0, 1,
             (long long)T * D, 0, (long long)T * D, 0, (long long)T * T, 0, 4, 8);

    sim_attn_kernel<<<dim3(T, Bb), 128>>>(QKb, QK2b, qa_rel, aq_rel, EQb, EKb, Gb, Pb, Wb);

    g_launch(0, Pb, Pb + 64, 0, Kb, Kb + (size_t)64 * D, 0, 0, 0, 0, PKb, PK2b, 0,
             T, D, 64, T, D, D, 0, 1,
             (long long)T * T, 0, (long long)T * D, 0, (long long)T * D, 0, 4, 8);

    final_kernel<<<Bb, 512>>>(PKb, PK2b, Wb, conceptE, clsw, clsb, out);
}